// round 11
// baseline (speedup 1.0000x reference)
#include <cuda_runtime.h>
#include <cuda_fp16.h>
#include <mma.h>
#include <math.h>
#include <stdint.h>

using namespace nvcuda;

#define NN 50000
#define NE 800000
#define DD 128
#define ND (NN * DD)
#define EPSF 1e-5f
#define NEGS 0.2f

#define GEMM_SMEM 69632

// ---------------- scratch (static device globals; no allocation) ----------------
__device__ __half g_xwh[ND];    // GCN transform * dinv[row]  (half, gather payload)
__device__ __half g_xlh[ND];    // GAT left transform (half, gather payload)
__device__ float g_xr[ND];      // GAT right transform (fp32)
__device__ float g_acc[ND];     // aggregation output (bias added, pre-LN, fp32)
__device__ __half g_wh[6 * DD * DD];  // fp16 weight copies
__device__ float g_dinv[NN];    // deg^{-1/2}
__device__ int   g_cnt[NN];     // in-degree histogram (no self loop)
__device__ int   g_off[NN + 1]; // CSR offsets
__device__ int   g_cur[NN];     // scatter cursors
__device__ int   g_csrc[NE];    // CSR: src node per incoming edge
__device__ int   g_bsum[64];    // scan block totals
__device__ double g_red[8];     // (sum,sumsq) x 4 LN slots

typedef unsigned long long ull;

// ---------------- packed f32x2 helpers (Blackwell; PTX-only ops) ----------------
__device__ __forceinline__ ull pk2(float a, float b) {
    ull r; asm("mov.b64 %0, {%1, %2};" : "=l"(r) : "f"(a), "f"(b)); return r;
}
__device__ __forceinline__ void upk2(ull p, float& a, float& b) {
    asm("mov.b64 {%0, %1}, %2;" : "=f"(a), "=f"(b) : "l"(p));
}
__device__ __forceinline__ ull fma2(ull a, ull b, ull c) {
    ull r; asm("fma.rn.f32x2 %0, %1, %2, %3;" : "=l"(r) : "l"(a), "l"(b), "l"(c)); return r;
}
__device__ __forceinline__ ull mul2p(ull a, ull b) {
    ull r; asm("mul.rn.f32x2 %0, %1, %2;" : "=l"(r) : "l"(a), "l"(b)); return r;
}
__device__ __forceinline__ ull add2p(ull a, ull b) {
    ull r; asm("add.rn.f32x2 %0, %1, %2;" : "=l"(r) : "l"(a), "l"(b)); return r;
}
__device__ __forceinline__ ull abs2p(ull a) {
    ull r; asm("and.b64 %0, %1, 0x7FFFFFFF7FFFFFFF;" : "=l"(r) : "l"(a)); return r;
}
__device__ __forceinline__ void h4_to_2x2(uint2 raw, ull& p01, ull& p23) {
    float2 a = __half22float2(*(__half2*)&raw.x);
    float2 b = __half22float2(*(__half2*)&raw.y);
    p01 = pk2(a.x, a.y); p23 = pk2(b.x, b.y);
}

// ---------------- fused init: zero hist + LN slots, convert weights ------------
__global__ void k_init(const float* __restrict__ w0, const float* __restrict__ w1,
                       const float* __restrict__ w2, const float* __restrict__ w3,
                       const float* __restrict__ w4, const float* __restrict__ w5) {
    int i = blockIdx.x * blockDim.x + threadIdx.x;
    if (i < NN) g_cnt[i] = 0;
    if (i < 8) g_red[i] = 0.0;
    if (i < 6 * DD * DD) {
        const float* ws[6] = {w0, w1, w2, w3, w4, w5};
        int m = i >> 14;
        int o = i & 16383;
        g_wh[i] = __float2half_rn(ws[m][o]);
    }
}
__global__ void k_hist(const int* __restrict__ dst) {
    int e = blockIdx.x * blockDim.x + threadIdx.x;
    if (e < NE) atomicAdd(&g_cnt[dst[e]], 1);
}
__global__ void k_scan1() {
    __shared__ int warp_sums[32];
    int tid = threadIdx.x;
    int lane = tid & 31, wid = tid >> 5;
    int i = blockIdx.x * 1024 + tid;
    int v = (i < NN) ? g_cnt[i] : 0;
    int x = v;
#pragma unroll
    for (int o = 1; o < 32; o <<= 1) {
        int y = __shfl_up_sync(0xffffffffu, x, o);
        if (lane >= o) x += y;
    }
    if (lane == 31) warp_sums[wid] = x;
    __syncthreads();
    if (wid == 0) {
        int ws = warp_sums[lane];
#pragma unroll
        for (int o = 1; o < 32; o <<= 1) {
            int y = __shfl_up_sync(0xffffffffu, ws, o);
            if (lane >= o) ws += y;
        }
        warp_sums[lane] = ws;
    }
    __syncthreads();
    int incl = x + (wid ? warp_sums[wid - 1] : 0);
    if (i < NN) {
        g_off[i] = incl - v;
        g_dinv[i] = rsqrtf((float)v + 1.0f);
    }
    if (tid == 1023) g_bsum[blockIdx.x] = incl;
}
__global__ void k_scan3(int nblk) {
    __shared__ int sb[64];
    __shared__ int prefix;
    int tid = threadIdx.x;
    if (tid < 64) sb[tid] = (tid < nblk) ? g_bsum[tid] : 0;
    __syncthreads();
    if (tid == 0) {
        int need = blockIdx.x >> 2;
        int s = 0;
        for (int k = 0; k < need; k++) s += sb[k];
        prefix = s;
    }
    __syncthreads();
    int i = blockIdx.x * 256 + tid;
    if (i < NN) {
        int o = g_off[i] + prefix;
        g_off[i] = o;
        g_cur[i] = o;
    }
    if (i == 0) g_off[NN] = NE;
}
__global__ void k_scatter(const int* __restrict__ src, const int* __restrict__ dst) {
    int e = blockIdx.x * blockDim.x + threadIdx.x;
    if (e >= NE) return;
    int pos = atomicAdd(&g_cur[dst[e]], 1);
    g_csrc[pos] = src[e];
}

// ---------------- tensor-core GEMM with fused input-LayerNorm+ReLU ----------------
// rowscale (nullable): multiply output row r by rowscale[r] before half convert
template <bool LNIN, bool PAIR>
__global__ void __launch_bounds__(256) gemm128t(
        const float* __restrict__ A,
        const __half* __restrict__ Wa16, const float* __restrict__ ba, __half* __restrict__ houta,
        const __half* __restrict__ Wb16, const float* __restrict__ bb, float* __restrict__ foutb,
        int slot, const float* __restrict__ gm, const float* __restrict__ bt,
        const float* __restrict__ rowscale) {
    extern __shared__ char smem[];
    __half (*Ah)[136]  = (__half(*)[136])smem;
    __half (*Wsh)[136] = (__half(*)[136])(smem + 34816);

    bool second = PAIR && (blockIdx.y != 0);
    const __half* W16  = second ? Wb16 : Wa16;
    const float*  bias = second ? bb : ba;

    int t = threadIdx.x;
    int row0 = blockIdx.x * 128;

    float fmu = 0.f, finv = 0.f;
    if (LNIN) {
        double mu = g_red[2 * slot] * (1.0 / (double)ND);
        double var = g_red[2 * slot + 1] * (1.0 / (double)ND) - mu * mu;
        fmu = (float)mu;
        finv = 1.0f / (sqrtf(fmaxf((float)var, 0.0f)) + EPSF);
    }

#pragma unroll
    for (int j = 0; j < 8; j++) {
        int u = t + j * 256;
        int lin = u * 8;
        int r = lin >> 7, c = lin & 127;
        *(uint4*)&Wsh[r][c] = *(const uint4*)(W16 + (size_t)r * 128 + c);
    }
#pragma unroll
    for (int j = 0; j < 16; j++) {
        int f = t + j * 256;
        int lin = f * 4;
        int r = lin >> 7, c = lin & 127;
        int gr = row0 + r;
        float4 v = (gr < NN) ? *(const float4*)(A + (size_t)gr * 128 + c)
                             : make_float4(0.f, 0.f, 0.f, 0.f);
        if (LNIN) {
            float4 gv = *(const float4*)(gm + c);
            float4 bv = *(const float4*)(bt + c);
            v.x = fmaxf((v.x - fmu) * finv * gv.x + bv.x, 0.f);
            v.y = fmaxf((v.y - fmu) * finv * gv.y + bv.y, 0.f);
            v.z = fmaxf((v.z - fmu) * finv * gv.z + bv.z, 0.f);
            v.w = fmaxf((v.w - fmu) * finv * gv.w + bv.w, 0.f);
        }
        __half2* dsth = (__half2*)&Ah[r][c];
        dsth[0] = __floats2half2_rn(v.x, v.y);
        dsth[1] = __floats2half2_rn(v.z, v.w);
    }
    __syncthreads();

    int w = t >> 5;
    int lane = t & 31;

    wmma::fragment<wmma::accumulator, 16, 16, 16, float> acc[8];
#pragma unroll
    for (int n = 0; n < 8; n++) wmma::fill_fragment(acc[n], 0.0f);

#pragma unroll
    for (int k = 0; k < 8; k++) {
        wmma::fragment<wmma::matrix_a, 16, 16, 16, __half, wmma::row_major> af;
        wmma::load_matrix_sync(af, &Ah[w * 16][k * 16], 136);
#pragma unroll
        for (int n = 0; n < 8; n++) {
            wmma::fragment<wmma::matrix_b, 16, 16, 16, __half, wmma::row_major> bf;
            wmma::load_matrix_sync(bf, &Wsh[k * 16][n * 16], 136);
            wmma::mma_sync(acc[n], af, bf, acc[n]);
        }
    }
    __syncthreads();

    float* stage = (float*)smem + (size_t)w * (16 * 136);
#pragma unroll
    for (int n = 0; n < 8; n++)
        wmma::store_matrix_sync(stage + n * 16, acc[n], 136, wmma::mem_row_major);
    __syncwarp();

    int row_in = lane >> 1;
    int c0 = (lane & 1) * 64;
    int gr = row0 + w * 16 + row_in;
    if (gr < NN) {
        float sc = (!second && rowscale) ? rowscale[gr] : 1.0f;
#pragma unroll
        for (int q = 0; q < 64; q += 8) {
            int colg = c0 + q;
            float4 v0 = *(float4*)(stage + row_in * 136 + colg);
            float4 v1 = *(float4*)(stage + row_in * 136 + colg + 4);
            if (bias) {
                float4 b0 = *(const float4*)(bias + colg);
                float4 b1 = *(const float4*)(bias + colg + 4);
                v0.x += b0.x; v0.y += b0.y; v0.z += b0.z; v0.w += b0.w;
                v1.x += b1.x; v1.y += b1.y; v1.z += b1.z; v1.w += b1.w;
            }
            if (second) {
                float* o = foutb + (size_t)gr * 128 + colg;
                *(float4*)(o)     = v0;
                *(float4*)(o + 4) = v1;
            } else {
                __half2 hh[4];
                hh[0] = __floats2half2_rn(v0.x * sc, v0.y * sc);
                hh[1] = __floats2half2_rn(v0.z * sc, v0.w * sc);
                hh[2] = __floats2half2_rn(v1.x * sc, v1.y * sc);
                hh[3] = __floats2half2_rn(v1.z * sc, v1.w * sc);
                *(uint4*)(houta + (size_t)gr * 128 + colg) = *(uint4*)hh;
            }
        }
    }
}

// ---------------- block epilogue: fused LN partial reduction ----------------
__device__ __forceinline__ void ln_block_reduce(float s, float s2, int slot) {
#pragma unroll
    for (int o = 16; o; o >>= 1) {
        s  += __shfl_xor_sync(0xffffffffu, s, o);
        s2 += __shfl_xor_sync(0xffffffffu, s2, o);
    }
    __shared__ float shs[8], shs2[8];
    int wid = threadIdx.x >> 5, lane = threadIdx.x & 31;
    if (lane == 0) { shs[wid] = s; shs2[wid] = s2; }
    __syncthreads();
    if (threadIdx.x == 0) {
        double ts = 0.0, t2 = 0.0;
        int nw = blockDim.x >> 5;
        for (int k = 0; k < nw; k++) { ts += (double)shs[k]; t2 += (double)shs2[k]; }
        atomicAdd(&g_red[2 * slot], ts);
        atomicAdd(&g_red[2 * slot + 1], t2);
    }
}

// ---------------- GCN aggregation (prescaled payload: pure sum) ----------------
// payload[s] = xw[s]*dinv[s]; out[d] = dinv[d] * sum_{s in N(d) u {d}} payload[s] + bias
__global__ void __launch_bounds__(256) k_gcn_csr(const float* __restrict__ bias, int slot) {
    int w = (blockIdx.x * blockDim.x + threadIdx.x) >> 5;
    int lane = threadIdx.x & 31;
    float s = 0.f, s2 = 0.f;
    if (w < NN) {
        float dd = g_dinv[w];
        uint2 rawS = *(const uint2*)(g_xwh + (size_t)w * 128 + lane * 4);
        ull a01, a23;
        h4_to_2x2(rawS, a01, a23);          // self payload
        int b = g_off[w], e = g_off[w + 1];
        int i = b;
        // peel to 16B alignment of csrc
        for (; i < e && (i & 3); i++) {
            uint2 rw = *(const uint2*)(g_xwh + (size_t)g_csrc[i] * 128 + lane * 4);
            ull u01, u23; h4_to_2x2(rw, u01, u23);
            a01 = add2p(a01, u01); a23 = add2p(a23, u23);
        }
        for (; i + 8 <= e; i += 8) {
            int4 c0 = *(const int4*)(g_csrc + i);
            int4 c1 = *(const int4*)(g_csrc + i + 4);
            uint2 r0 = *(const uint2*)(g_xwh + (size_t)c0.x * 128 + lane * 4);
            uint2 r1 = *(const uint2*)(g_xwh + (size_t)c0.y * 128 + lane * 4);
            uint2 r2 = *(const uint2*)(g_xwh + (size_t)c0.z * 128 + lane * 4);
            uint2 r3 = *(const uint2*)(g_xwh + (size_t)c0.w * 128 + lane * 4);
            uint2 r4 = *(const uint2*)(g_xwh + (size_t)c1.x * 128 + lane * 4);
            uint2 r5 = *(const uint2*)(g_xwh + (size_t)c1.y * 128 + lane * 4);
            uint2 r6 = *(const uint2*)(g_xwh + (size_t)c1.z * 128 + lane * 4);
            uint2 r7 = *(const uint2*)(g_xwh + (size_t)c1.w * 128 + lane * 4);
            ull u01, u23;
            h4_to_2x2(r0, u01, u23); a01 = add2p(a01, u01); a23 = add2p(a23, u23);
            h4_to_2x2(r1, u01, u23); a01 = add2p(a01, u01); a23 = add2p(a23, u23);
            h4_to_2x2(r2, u01, u23); a01 = add2p(a01, u01); a23 = add2p(a23, u23);
            h4_to_2x2(r3, u01, u23); a01 = add2p(a01, u01); a23 = add2p(a23, u23);
            h4_to_2x2(r4, u01, u23); a01 = add2p(a01, u01); a23 = add2p(a23, u23);
            h4_to_2x2(r5, u01, u23); a01 = add2p(a01, u01); a23 = add2p(a23, u23);
            h4_to_2x2(r6, u01, u23); a01 = add2p(a01, u01); a23 = add2p(a23, u23);
            h4_to_2x2(r7, u01, u23); a01 = add2p(a01, u01); a23 = add2p(a23, u23);
        }
        for (; i + 4 <= e; i += 4) {
            int4 c0 = *(const int4*)(g_csrc + i);
            uint2 r0 = *(const uint2*)(g_xwh + (size_t)c0.x * 128 + lane * 4);
            uint2 r1 = *(const uint2*)(g_xwh + (size_t)c0.y * 128 + lane * 4);
            uint2 r2 = *(const uint2*)(g_xwh + (size_t)c0.z * 128 + lane * 4);
            uint2 r3 = *(const uint2*)(g_xwh + (size_t)c0.w * 128 + lane * 4);
            ull u01, u23;
            h4_to_2x2(r0, u01, u23); a01 = add2p(a01, u01); a23 = add2p(a23, u23);
            h4_to_2x2(r1, u01, u23); a01 = add2p(a01, u01); a23 = add2p(a23, u23);
            h4_to_2x2(r2, u01, u23); a01 = add2p(a01, u01); a23 = add2p(a23, u23);
            h4_to_2x2(r3, u01, u23); a01 = add2p(a01, u01); a23 = add2p(a23, u23);
        }
        for (; i < e; i++) {
            uint2 rw = *(const uint2*)(g_xwh + (size_t)g_csrc[i] * 128 + lane * 4);
            ull u01, u23; h4_to_2x2(rw, u01, u23);
            a01 = add2p(a01, u01); a23 = add2p(a23, u23);
        }
        float4 b4 = ((const float4*)bias)[lane];
        float ax, ay, az, aw;
        upk2(a01, ax, ay); upk2(a23, az, aw);
        ax = ax * dd + b4.x; ay = ay * dd + b4.y;
        az = az * dd + b4.z; aw = aw * dd + b4.w;
        ((float4*)(g_acc + (size_t)w * 128))[lane] = make_float4(ax, ay, az, aw);
        s  = ax + ay + az + aw;
        s2 = ax * ax + ay * ay + az * az + aw * aw;
    }
    ln_block_reduce(s, s2, slot);
}

// ---------------- fused GATv2 (CSR gather + online softmax, int4 csrc) ----------
#define C06 0x3F19999A3F19999AULL   // (0.6f,0.6f)
#define C04 0x3ECCCCCD3ECCCCCDULL   // (0.4f,0.4f)

template <int H>
__device__ __forceinline__ float score2(ull l01, ull l23, ull r01, ull r23,
                                        ull a01, ull a23) {
    ull s01 = add2p(l01, r01), s23 = add2p(l23, r23);
    ull b01 = abs2p(s01),      b23 = abs2p(s23);
    ull t01 = fma2(b01, C04, mul2p(s01, C06));
    ull t23 = fma2(b23, C04, mul2p(s23, C06));
    ull qp  = fma2(t23, a23, mul2p(t01, a01));
    float qa, qb;
    upk2(qp, qa, qb);
    float q = qa + qb;
    if (H == 8) {
        q += __shfl_xor_sync(0xffffffffu, q, 1);
        q += __shfl_xor_sync(0xffffffffu, q, 2);
    } else {
#pragma unroll
        for (int o = 16; o; o >>= 1) q += __shfl_xor_sync(0xffffffffu, q, o);
    }
    return q;
}

template <int H>
__global__ void __launch_bounds__(256) k_gat_csr(const float* __restrict__ att,
                                                 const float* __restrict__ bias, int slot) {
    int w = (blockIdx.x * blockDim.x + threadIdx.x) >> 5;
    int lane = threadIdx.x & 31;
    float ps = 0.f, ps2 = 0.f;
    if (w < NN) {
        float4 r4 = ((const float4*)(g_xr + (size_t)w * 128))[lane];
        float4 a4 = ((const float4*)att)[lane];
        ull r01 = pk2(r4.x, r4.y), r23 = pk2(r4.z, r4.w);
        ull a01 = pk2(a4.x, a4.y), a23 = pk2(a4.z, a4.w);

        uint2 rawl = *(const uint2*)(g_xlh + (size_t)w * 128 + lane * 4);
        ull l01, l23;
        h4_to_2x2(rawl, l01, l23);
        float m = score2<H>(l01, l23, r01, r23, a01, a23);
        float den = 1.0f;
        ull acc01 = l01, acc23 = l23;

        int b = g_off[w], e = g_off[w + 1];
        int i = b;
        // peel to alignment
        for (; i < e && (i & 3); i++) {
            uint2 vr = *(const uint2*)(g_xlh + (size_t)g_csrc[i] * 128 + lane * 4);
            ull ua, ub; h4_to_2x2(vr, ua, ub);
            float q = score2<H>(ua, ub, r01, r23, a01, a23);
            float nm = fmaxf(m, q);
            float so = __expf(m - nm), wg = __expf(q - nm);
            den = den * so + wg;
            ull so2 = pk2(so, so), wg2 = pk2(wg, wg);
            acc01 = fma2(ua, wg2, mul2p(acc01, so2));
            acc23 = fma2(ub, wg2, mul2p(acc23, so2));
            m = nm;
        }
        for (; i + 4 <= e; i += 4) {
            int4 c = *(const int4*)(g_csrc + i);
            uint2 w0r = *(const uint2*)(g_xlh + (size_t)c.x * 128 + lane * 4);
            uint2 w1r = *(const uint2*)(g_xlh + (size_t)c.y * 128 + lane * 4);
            uint2 w2r = *(const uint2*)(g_xlh + (size_t)c.z * 128 + lane * 4);
            uint2 w3r = *(const uint2*)(g_xlh + (size_t)c.w * 128 + lane * 4);
            ull u0a, u0b, u1a, u1b, u2a, u2b, u3a, u3b;
            h4_to_2x2(w0r, u0a, u0b);
            h4_to_2x2(w1r, u1a, u1b);
            h4_to_2x2(w2r, u2a, u2b);
            h4_to_2x2(w3r, u3a, u3b);
            float q0 = score2<H>(u0a, u0b, r01, r23, a01, a23);
            float q1 = score2<H>(u1a, u1b, r01, r23, a01, a23);
            float q2 = score2<H>(u2a, u2b, r01, r23, a01, a23);
            float q3 = score2<H>(u3a, u3b, r01, r23, a01, a23);
            float nm = fmaxf(fmaxf(fmaxf(q0, q1), fmaxf(q2, q3)), m);
            float so = __expf(m - nm);
            float w0 = __expf(q0 - nm), w1 = __expf(q1 - nm);
            float w2 = __expf(q2 - nm), w3 = __expf(q3 - nm);
            den = den * so + w0 + w1 + w2 + w3;
            ull so2 = pk2(so, so);
            ull w0p = pk2(w0, w0), w1p = pk2(w1, w1);
            ull w2p = pk2(w2, w2), w3p = pk2(w3, w3);
            acc01 = mul2p(acc01, so2);
            acc01 = fma2(u0a, w0p, acc01);
            acc01 = fma2(u1a, w1p, acc01);
            acc01 = fma2(u2a, w2p, acc01);
            acc01 = fma2(u3a, w3p, acc01);
            acc23 = mul2p(acc23, so2);
            acc23 = fma2(u0b, w0p, acc23);
            acc23 = fma2(u1b, w1p, acc23);
            acc23 = fma2(u2b, w2p, acc23);
            acc23 = fma2(u3b, w3p, acc23);
            m = nm;
        }
        for (; i < e; i++) {
            uint2 vr = *(const uint2*)(g_xlh + (size_t)g_csrc[i] * 128 + lane * 4);
            ull ua, ub; h4_to_2x2(vr, ua, ub);
            float q = score2<H>(ua, ub, r01, r23, a01, a23);
            float nm = fmaxf(m, q);
            float so = __expf(m - nm), wg = __expf(q - nm);
            den = den * so + wg;
            ull so2 = pk2(so, so), wg2 = pk2(wg, wg);
            acc01 = fma2(ua, wg2, mul2p(acc01, so2));
            acc23 = fma2(ub, wg2, mul2p(acc23, so2));
            m = nm;
        }
        float inv = 1.0f / den;
        float4 b4 = ((const float4*)bias)[lane];
        float ax, ay, az, aw;
        upk2(acc01, ax, ay); upk2(acc23, az, aw);
        ax = ax * inv + b4.x;
        ay = ay * inv + b4.y;
        az = az * inv + b4.z;
        aw = aw * inv + b4.w;
        ((float4*)(g_acc + (size_t)w * 128))[lane] = make_float4(ax, ay, az, aw);
        ps  = ax + ay + az + aw;
        ps2 = ax * ax + ay * ay + az * az + aw * aw;
    }
    ln_block_reduce(ps, ps2, slot);
}

// ---------------- LayerNorm apply (final layer only) ----------------
__global__ void k_ln_apply(const float* __restrict__ in,
                           const float* __restrict__ gm, const float* __restrict__ bt,
                           float* __restrict__ out, int slot) {
    int i = blockIdx.x * blockDim.x + threadIdx.x;
    if (i >= ND) return;
    double mu = g_red[2 * slot] * (1.0 / (double)ND);
    double var = g_red[2 * slot + 1] * (1.0 / (double)ND) - mu * mu;
    float inv = 1.0f / (sqrtf(fmaxf((float)var, 0.0f)) + EPSF);
    int c = i & 127;
    float v = in[i];
    out[i] = (v - (float)mu) * inv * gm[c] + bt[c];
}

// ---------------- launch ----------------
static inline int gridFor(long long n, int blk) { return (int)((n + blk - 1) / blk); }

extern "C" void kernel_launch(void* const* d_in, const int* in_sizes, int n_in,
                              void* d_out, int out_size) {
    const float* x   = (const float*)d_in[0];
    const int*   ei  = (const int*)d_in[1];
    const float* W0  = (const float*)d_in[2];
    const float* b0  = (const float*)d_in[3];
    const float* g0  = (const float*)d_in[4];
    const float* be0 = (const float*)d_in[5];
    const float* Wl1 = (const float*)d_in[6];
    const float* bl1 = (const float*)d_in[7];
    const float* Wr1 = (const float*)d_in[8];
    const float* br1 = (const float*)d_in[9];
    const float* att1= (const float*)d_in[10];
    const float* bg1 = (const float*)d_in[11];
    const float* g1  = (const float*)d_in[12];
    const float* be1 = (const float*)d_in[13];
    const float* W2  = (const float*)d_in[14];
    const float* b2  = (const float*)d_in[15];
    const float* g2  = (const float*)d_in[16];
    const float* be2 = (const float*)d_in[17];
    const float* Wl3 = (const float*)d_in[18];
    const float* bl3 = (const float*)d_in[19];
    const float* Wr3 = (const float*)d_in[20];
    const float* br3 = (const float*)d_in[21];
    const float* att3= (const float*)d_in[22];
    const float* bg3 = (const float*)d_in[23];
    const float* g3  = (const float*)d_in[24];
    const float* be3 = (const float*)d_in[25];
    float* out = (float*)d_out;

    const int* src = ei;
    const int* dst = ei + NE;

    const int BLK = 256;
    const int gE   = gridFor(NE, BLK);
    const int gND  = gridFor(ND, BLK);
    const int gNW  = gridFor((long long)NN * 32, BLK);
    const int nGemmX = gridFor(NN, 128);
    const dim3 gG1(nGemmX, 1), gG2(nGemmX, 2);
    const int nScanBlk = gridFor(NN, 1024);
    const int gInit = gridFor(6 * DD * DD, BLK);
    const int gN256 = gridFor(NN, 256);

    __half* p_xwh; cudaGetSymbolAddress((void**)&p_xwh, g_xwh);
    __half* p_xlh; cudaGetSymbolAddress((void**)&p_xlh, g_xlh);
    float* p_xr;  cudaGetSymbolAddress((void**)&p_xr, g_xr);
    float* p_acc; cudaGetSymbolAddress((void**)&p_acc, g_acc);
    float* p_dinv; cudaGetSymbolAddress((void**)&p_dinv, g_dinv);
    __half* p_wh; cudaGetSymbolAddress((void**)&p_wh, g_wh);

    const __half* w0h  = p_wh;
    const __half* wl1h = p_wh + 1 * DD * DD;
    const __half* wr1h = p_wh + 2 * DD * DD;
    const __half* w2h  = p_wh + 3 * DD * DD;
    const __half* wl3h = p_wh + 4 * DD * DD;
    const __half* wr3h = p_wh + 5 * DD * DD;

    static bool attr_done = false;
    if (!attr_done) {
        cudaFuncSetAttribute(gemm128t<false, false>,
                             cudaFuncAttributeMaxDynamicSharedMemorySize, GEMM_SMEM);
        cudaFuncSetAttribute(gemm128t<true, false>,
                             cudaFuncAttributeMaxDynamicSharedMemorySize, GEMM_SMEM);
        cudaFuncSetAttribute(gemm128t<true, true>,
                             cudaFuncAttributeMaxDynamicSharedMemorySize, GEMM_SMEM);
        attr_done = true;
    }

    // CSR front; g_dinv ready after scan1, consumed by all GCN gemms
    k_init<<<gInit, BLK>>>(W0, Wl1, Wr1, W2, Wl3, Wr3);
    k_hist<<<gE, BLK>>>(dst);
    k_scan1<<<nScanBlk, 1024>>>();
    gemm128t<false, false><<<gG1, BLK, GEMM_SMEM>>>(x, w0h, nullptr, p_xwh,
                                                    nullptr, nullptr, nullptr, 0, nullptr, nullptr,
                                                    p_dinv);
    k_scan3<<<gN256, 256>>>(nScanBlk);
    k_scatter<<<gE, BLK>>>(src, dst);

    // ---- layer 0: GCN agg ----
    k_gcn_csr<<<gNW, BLK>>>(b0, 0);

    // ---- layer 1: GATv2 (H=8) ----
    gemm128t<true, true><<<gG2, BLK, GEMM_SMEM>>>(p_acc, wl1h, bl1, p_xlh,
                                                  wr1h, br1, p_xr, 0, g0, be0, nullptr);
    k_gat_csr<8><<<gNW, BLK>>>(att1, bg1, 1);

    // ---- layer 2: GCN ----
    gemm128t<true, false><<<gG1, BLK, GEMM_SMEM>>>(p_acc, w2h, nullptr, p_xwh,
                                                   nullptr, nullptr, nullptr, 1, g1, be1,
                                                   p_dinv);
    k_gcn_csr<<<gNW, BLK>>>(b2, 2);

    // ---- layer 3: GATv2 (H=1) ----
    gemm128t<true, true><<<gG2, BLK, GEMM_SMEM>>>(p_acc, wl3h, bl3, p_xlh,
                                                  wr3h, br3, p_xr, 2, g2, be2, nullptr);
    k_gat_csr<1><<<gNW, BLK>>>(att3, bg3, 3);

    // ---- final LN -> output ----
    k_ln_apply<<<gND, BLK>>>(p_acc, g3, be3, out, 3);
}

// round 13
// speedup vs baseline: 1.0254x; 1.0254x over previous
#include <cuda_runtime.h>
#include <cuda_fp16.h>
#include <mma.h>
#include <math.h>
#include <stdint.h>

using namespace nvcuda;

#define NN 50000
#define NE 800000
#define DD 128
#define ND (NN * DD)
#define EPSF 1e-5f
#define NEGS 0.2f

#define GEMM_SMEM 69632

// ---------------- scratch (static device globals; no allocation) ----------------
__device__ __half g_xwh[ND];    // GCN transform * dinv[row]  (half, gather payload)
__device__ __half g_xlh[ND];    // GAT left transform (half, gather payload)
__device__ float g_xr[ND];      // GAT right transform (fp32)
__device__ float g_acc[ND];     // aggregation output (bias added, pre-LN, fp32)
__device__ __half g_wh[6 * DD * DD];  // fp16 weight copies
__device__ float g_dinv[NN];    // deg^{-1/2}
__device__ int   g_cnt[NN];     // in-degree histogram (no self loop)
__device__ int   g_off[NN + 1]; // CSR offsets
__device__ int   g_cur[NN];     // scatter cursors
__device__ int   g_csrc[NE];    // CSR: src node per incoming edge
__device__ int   g_bsum[64];    // scan block totals
__device__ double g_red[8];     // (sum,sumsq) x 4 LN slots

typedef unsigned long long ull;

// ---------------- packed f32x2 helpers ----------------
__device__ __forceinline__ ull pk2(float a, float b) {
    ull r; asm("mov.b64 %0, {%1, %2};" : "=l"(r) : "f"(a), "f"(b)); return r;
}
__device__ __forceinline__ void upk2(ull p, float& a, float& b) {
    asm("mov.b64 {%0, %1}, %2;" : "=f"(a), "=f"(b) : "l"(p));
}
__device__ __forceinline__ ull fma2(ull a, ull b, ull c) {
    ull r; asm("fma.rn.f32x2 %0, %1, %2, %3;" : "=l"(r) : "l"(a), "l"(b), "l"(c)); return r;
}
__device__ __forceinline__ ull mul2p(ull a, ull b) {
    ull r; asm("mul.rn.f32x2 %0, %1, %2;" : "=l"(r) : "l"(a), "l"(b)); return r;
}
__device__ __forceinline__ ull add2p(ull a, ull b) {
    ull r; asm("add.rn.f32x2 %0, %1, %2;" : "=l"(r) : "l"(a), "l"(b)); return r;
}
__device__ __forceinline__ ull abs2p(ull a) {
    ull r; asm("and.b64 %0, %1, 0x7FFFFFFF7FFFFFFF;" : "=l"(r) : "l"(a)); return r;
}
__device__ __forceinline__ void h4_to_2x2(uint2 raw, ull& p01, ull& p23) {
    float2 a = __half22float2(*(__half2*)&raw.x);
    float2 b = __half22float2(*(__half2*)&raw.y);
    p01 = pk2(a.x, a.y); p23 = pk2(b.x, b.y);
}

// ---------------- fused init: zero hist + LN slots, convert weights ------------
__global__ void k_init(const float* __restrict__ w0, const float* __restrict__ w1,
                       const float* __restrict__ w2, const float* __restrict__ w3,
                       const float* __restrict__ w4, const float* __restrict__ w5) {
    int i = blockIdx.x * blockDim.x + threadIdx.x;
    if (i < NN) g_cnt[i] = 0;
    if (i < 8) g_red[i] = 0.0;
    if (i < 6 * DD * DD) {
        const float* ws[6] = {w0, w1, w2, w3, w4, w5};
        int m = i >> 14;
        int o = i & 16383;
        g_wh[i] = __float2half_rn(ws[m][o]);
    }
}
__global__ void k_hist(const int* __restrict__ dst) {
    int e = blockIdx.x * blockDim.x + threadIdx.x;
    if (e < NE) atomicAdd(&g_cnt[dst[e]], 1);
}
__global__ void k_scan1() {
    __shared__ int warp_sums[32];
    int tid = threadIdx.x;
    int lane = tid & 31, wid = tid >> 5;
    int i = blockIdx.x * 1024 + tid;
    int v = (i < NN) ? g_cnt[i] : 0;
    int x = v;
#pragma unroll
    for (int o = 1; o < 32; o <<= 1) {
        int y = __shfl_up_sync(0xffffffffu, x, o);
        if (lane >= o) x += y;
    }
    if (lane == 31) warp_sums[wid] = x;
    __syncthreads();
    if (wid == 0) {
        int ws = warp_sums[lane];
#pragma unroll
        for (int o = 1; o < 32; o <<= 1) {
            int y = __shfl_up_sync(0xffffffffu, ws, o);
            if (lane >= o) ws += y;
        }
        warp_sums[lane] = ws;
    }
    __syncthreads();
    int incl = x + (wid ? warp_sums[wid - 1] : 0);
    if (i < NN) {
        g_off[i] = incl - v;
        g_dinv[i] = rsqrtf((float)v + 1.0f);
    }
    if (tid == 1023) g_bsum[blockIdx.x] = incl;
}
__global__ void k_scan3(int nblk) {
    __shared__ int sb[64];
    __shared__ int prefix;
    int tid = threadIdx.x;
    if (tid < 64) sb[tid] = (tid < nblk) ? g_bsum[tid] : 0;
    __syncthreads();
    if (tid == 0) {
        int need = blockIdx.x >> 2;
        int s = 0;
        for (int k = 0; k < need; k++) s += sb[k];
        prefix = s;
    }
    __syncthreads();
    int i = blockIdx.x * 256 + tid;
    if (i < NN) {
        int o = g_off[i] + prefix;
        g_off[i] = o;
        g_cur[i] = o;
    }
    if (i == 0) g_off[NN] = NE;
}
__global__ void k_scatter(const int* __restrict__ src, const int* __restrict__ dst) {
    int e = blockIdx.x * blockDim.x + threadIdx.x;
    if (e >= NE) return;
    int pos = atomicAdd(&g_cur[dst[e]], 1);
    g_csrc[pos] = src[e];
}

// ---------------- tensor-core GEMM with fused input-LayerNorm+ReLU ----------------
template <bool LNIN, bool PAIR>
__global__ void __launch_bounds__(256) gemm128t(
        const float* __restrict__ A,
        const __half* __restrict__ Wa16, const float* __restrict__ ba, __half* __restrict__ houta,
        const __half* __restrict__ Wb16, const float* __restrict__ bb, float* __restrict__ foutb,
        int slot, const float* __restrict__ gm, const float* __restrict__ bt,
        const float* __restrict__ rowscale) {
    extern __shared__ char smem[];
    __half (*Ah)[136]  = (__half(*)[136])smem;
    __half (*Wsh)[136] = (__half(*)[136])(smem + 34816);

    bool second = PAIR && (blockIdx.y != 0);
    const __half* W16  = second ? Wb16 : Wa16;
    const float*  bias = second ? bb : ba;

    int t = threadIdx.x;
    int row0 = blockIdx.x * 128;

    float fmu = 0.f, finv = 0.f;
    if (LNIN) {
        double mu = g_red[2 * slot] * (1.0 / (double)ND);
        double var = g_red[2 * slot + 1] * (1.0 / (double)ND) - mu * mu;
        fmu = (float)mu;
        finv = 1.0f / (sqrtf(fmaxf((float)var, 0.0f)) + EPSF);
    }

#pragma unroll
    for (int j = 0; j < 8; j++) {
        int u = t + j * 256;
        int lin = u * 8;
        int r = lin >> 7, c = lin & 127;
        *(uint4*)&Wsh[r][c] = *(const uint4*)(W16 + (size_t)r * 128 + c);
    }
#pragma unroll
    for (int j = 0; j < 16; j++) {
        int f = t + j * 256;
        int lin = f * 4;
        int r = lin >> 7, c = lin & 127;
        int gr = row0 + r;
        float4 v = (gr < NN) ? *(const float4*)(A + (size_t)gr * 128 + c)
                             : make_float4(0.f, 0.f, 0.f, 0.f);
        if (LNIN) {
            float4 gv = *(const float4*)(gm + c);
            float4 bv = *(const float4*)(bt + c);
            v.x = fmaxf((v.x - fmu) * finv * gv.x + bv.x, 0.f);
            v.y = fmaxf((v.y - fmu) * finv * gv.y + bv.y, 0.f);
            v.z = fmaxf((v.z - fmu) * finv * gv.z + bv.z, 0.f);
            v.w = fmaxf((v.w - fmu) * finv * gv.w + bv.w, 0.f);
        }
        __half2* dsth = (__half2*)&Ah[r][c];
        dsth[0] = __floats2half2_rn(v.x, v.y);
        dsth[1] = __floats2half2_rn(v.z, v.w);
    }
    __syncthreads();

    int w = t >> 5;
    int lane = t & 31;

    wmma::fragment<wmma::accumulator, 16, 16, 16, float> acc[8];
#pragma unroll
    for (int n = 0; n < 8; n++) wmma::fill_fragment(acc[n], 0.0f);

#pragma unroll
    for (int k = 0; k < 8; k++) {
        wmma::fragment<wmma::matrix_a, 16, 16, 16, __half, wmma::row_major> af;
        wmma::load_matrix_sync(af, &Ah[w * 16][k * 16], 136);
#pragma unroll
        for (int n = 0; n < 8; n++) {
            wmma::fragment<wmma::matrix_b, 16, 16, 16, __half, wmma::row_major> bf;
            wmma::load_matrix_sync(bf, &Wsh[k * 16][n * 16], 136);
            wmma::mma_sync(acc[n], af, bf, acc[n]);
        }
    }
    __syncthreads();

    float* stage = (float*)smem + (size_t)w * (16 * 136);
#pragma unroll
    for (int n = 0; n < 8; n++)
        wmma::store_matrix_sync(stage + n * 16, acc[n], 136, wmma::mem_row_major);
    __syncwarp();

    int row_in = lane >> 1;
    int c0 = (lane & 1) * 64;
    int gr = row0 + w * 16 + row_in;
    if (gr < NN) {
        float sc = (!second && rowscale) ? rowscale[gr] : 1.0f;
#pragma unroll
        for (int q = 0; q < 64; q += 8) {
            int colg = c0 + q;
            float4 v0 = *(float4*)(stage + row_in * 136 + colg);
            float4 v1 = *(float4*)(stage + row_in * 136 + colg + 4);
            if (bias) {
                float4 b0 = *(const float4*)(bias + colg);
                float4 b1 = *(const float4*)(bias + colg + 4);
                v0.x += b0.x; v0.y += b0.y; v0.z += b0.z; v0.w += b0.w;
                v1.x += b1.x; v1.y += b1.y; v1.z += b1.z; v1.w += b1.w;
            }
            if (second) {
                float* o = foutb + (size_t)gr * 128 + colg;
                *(float4*)(o)     = v0;
                *(float4*)(o + 4) = v1;
            } else {
                __half2 hh[4];
                hh[0] = __floats2half2_rn(v0.x * sc, v0.y * sc);
                hh[1] = __floats2half2_rn(v0.z * sc, v0.w * sc);
                hh[2] = __floats2half2_rn(v1.x * sc, v1.y * sc);
                hh[3] = __floats2half2_rn(v1.z * sc, v1.w * sc);
                *(uint4*)(houta + (size_t)gr * 128 + colg) = *(uint4*)hh;
            }
        }
    }
}

// ---------------- block epilogue: fused LN partial reduction ----------------
__device__ __forceinline__ void ln_block_reduce(float s, float s2, int slot) {
#pragma unroll
    for (int o = 16; o; o >>= 1) {
        s  += __shfl_xor_sync(0xffffffffu, s, o);
        s2 += __shfl_xor_sync(0xffffffffu, s2, o);
    }
    __shared__ float shs[8], shs2[8];
    int wid = threadIdx.x >> 5, lane = threadIdx.x & 31;
    if (lane == 0) { shs[wid] = s; shs2[wid] = s2; }
    __syncthreads();
    if (threadIdx.x == 0) {
        double ts = 0.0, t2 = 0.0;
        int nw = blockDim.x >> 5;
        for (int k = 0; k < nw; k++) { ts += (double)shs[k]; t2 += (double)shs2[k]; }
        atomicAdd(&g_red[2 * slot], ts);
        atomicAdd(&g_red[2 * slot + 1], t2);
    }
}

// ---------------- GCN aggregation (prescaled payload: pure sum, chunk-8) --------
__global__ void __launch_bounds__(256) k_gcn_csr(const float* __restrict__ bias, int slot) {
    int w = (blockIdx.x * blockDim.x + threadIdx.x) >> 5;
    int lane = threadIdx.x & 31;
    float s = 0.f, s2 = 0.f;
    if (w < NN) {
        float dd = g_dinv[w];
        uint2 rawS = *(const uint2*)(g_xwh + (size_t)w * 128 + lane * 4);
        ull a01, a23;
        h4_to_2x2(rawS, a01, a23);          // self payload (already * dinv[self])
        int b = g_off[w], e = g_off[w + 1];
        int i = b;
        for (; i + 8 <= e; i += 8) {
            int si[8];
#pragma unroll
            for (int j = 0; j < 8; j++) si[j] = g_csrc[i + j];
            uint2 raw[8];
#pragma unroll
            for (int j = 0; j < 8; j++)
                raw[j] = *(const uint2*)(g_xwh + (size_t)si[j] * 128 + lane * 4);
#pragma unroll
            for (int j = 0; j < 8; j++) {
                ull u01, u23;
                h4_to_2x2(raw[j], u01, u23);
                a01 = add2p(a01, u01);
                a23 = add2p(a23, u23);
            }
        }
        for (; i < e; i++) {
            uint2 rw = *(const uint2*)(g_xwh + (size_t)g_csrc[i] * 128 + lane * 4);
            ull u01, u23; h4_to_2x2(rw, u01, u23);
            a01 = add2p(a01, u01); a23 = add2p(a23, u23);
        }
        float4 b4 = ((const float4*)bias)[lane];
        float ax, ay, az, aw;
        upk2(a01, ax, ay); upk2(a23, az, aw);
        ax = ax * dd + b4.x; ay = ay * dd + b4.y;
        az = az * dd + b4.z; aw = aw * dd + b4.w;
        ((float4*)(g_acc + (size_t)w * 128))[lane] = make_float4(ax, ay, az, aw);
        s  = ax + ay + az + aw;
        s2 = ax * ax + ay * ay + az * az + aw * aw;
    }
    ln_block_reduce(s, s2, slot);
}

// ---------------- fused GATv2 (CSR gather + online softmax, chunk-4) ------------
#define C06 0x3F19999A3F19999AULL
#define C04 0x3ECCCCCD3ECCCCCDULL

template <int H>
__device__ __forceinline__ float score2(ull l01, ull l23, ull r01, ull r23,
                                        ull a01, ull a23) {
    ull s01 = add2p(l01, r01), s23 = add2p(l23, r23);
    ull b01 = abs2p(s01),      b23 = abs2p(s23);
    ull t01 = fma2(b01, C04, mul2p(s01, C06));
    ull t23 = fma2(b23, C04, mul2p(s23, C06));
    ull qp  = fma2(t23, a23, mul2p(t01, a01));
    float qa, qb;
    upk2(qp, qa, qb);
    float q = qa + qb;
    if (H == 8) {
        q += __shfl_xor_sync(0xffffffffu, q, 1);
        q += __shfl_xor_sync(0xffffffffu, q, 2);
    } else {
#pragma unroll
        for (int o = 16; o; o >>= 1) q += __shfl_xor_sync(0xffffffffu, q, o);
    }
    return q;
}

template <int H>
__global__ void __launch_bounds__(256) k_gat_csr(const float* __restrict__ att,
                                                 const float* __restrict__ bias, int slot) {
    int w = (blockIdx.x * blockDim.x + threadIdx.x) >> 5;
    int lane = threadIdx.x & 31;
    float ps = 0.f, ps2 = 0.f;
    if (w < NN) {
        float4 r4 = ((const float4*)(g_xr + (size_t)w * 128))[lane];
        float4 a4 = ((const float4*)att)[lane];
        ull r01 = pk2(r4.x, r4.y), r23 = pk2(r4.z, r4.w);
        ull a01 = pk2(a4.x, a4.y), a23 = pk2(a4.z, a4.w);

        uint2 rawl = *(const uint2*)(g_xlh + (size_t)w * 128 + lane * 4);
        ull l01, l23;
        h4_to_2x2(rawl, l01, l23);
        float m = score2<H>(l01, l23, r01, r23, a01, a23);
        float den = 1.0f;
        ull acc01 = l01, acc23 = l23;

        int b = g_off[w], e = g_off[w + 1];
        int i = b;
        for (; i + 4 <= e; i += 4) {
            int s0 = g_csrc[i], s1 = g_csrc[i + 1], s2 = g_csrc[i + 2], s3 = g_csrc[i + 3];
            uint2 w0r = *(const uint2*)(g_xlh + (size_t)s0 * 128 + lane * 4);
            uint2 w1r = *(const uint2*)(g_xlh + (size_t)s1 * 128 + lane * 4);
            uint2 w2r = *(const uint2*)(g_xlh + (size_t)s2 * 128 + lane * 4);
            uint2 w3r = *(const uint2*)(g_xlh + (size_t)s3 * 128 + lane * 4);
            ull u0a, u0b, u1a, u1b, u2a, u2b, u3a, u3b;
            h4_to_2x2(w0r, u0a, u0b);
            h4_to_2x2(w1r, u1a, u1b);
            h4_to_2x2(w2r, u2a, u2b);
            h4_to_2x2(w3r, u3a, u3b);
            float q0 = score2<H>(u0a, u0b, r01, r23, a01, a23);
            float q1 = score2<H>(u1a, u1b, r01, r23, a01, a23);
            float q2 = score2<H>(u2a, u2b, r01, r23, a01, a23);
            float q3 = score2<H>(u3a, u3b, r01, r23, a01, a23);
            float nm = fmaxf(fmaxf(fmaxf(q0, q1), fmaxf(q2, q3)), m);
            float so = __expf(m - nm);
            float w0 = __expf(q0 - nm), w1 = __expf(q1 - nm);
            float w2 = __expf(q2 - nm), w3 = __expf(q3 - nm);
            den = den * so + w0 + w1 + w2 + w3;
            ull so2 = pk2(so, so);
            ull w0p = pk2(w0, w0), w1p = pk2(w1, w1);
            ull w2p = pk2(w2, w2), w3p = pk2(w3, w3);
            acc01 = mul2p(acc01, so2);
            acc01 = fma2(u0a, w0p, acc01);
            acc01 = fma2(u1a, w1p, acc01);
            acc01 = fma2(u2a, w2p, acc01);
            acc01 = fma2(u3a, w3p, acc01);
            acc23 = mul2p(acc23, so2);
            acc23 = fma2(u0b, w0p, acc23);
            acc23 = fma2(u1b, w1p, acc23);
            acc23 = fma2(u2b, w2p, acc23);
            acc23 = fma2(u3b, w3p, acc23);
            m = nm;
        }
        for (; i < e; i++) {
            uint2 vr = *(const uint2*)(g_xlh + (size_t)g_csrc[i] * 128 + lane * 4);
            ull ua, ub; h4_to_2x2(vr, ua, ub);
            float q = score2<H>(ua, ub, r01, r23, a01, a23);
            float nm = fmaxf(m, q);
            float so = __expf(m - nm), wg = __expf(q - nm);
            den = den * so + wg;
            ull so2 = pk2(so, so), wg2 = pk2(wg, wg);
            acc01 = fma2(ua, wg2, mul2p(acc01, so2));
            acc23 = fma2(ub, wg2, mul2p(acc23, so2));
            m = nm;
        }
        float inv = 1.0f / den;
        float4 b4 = ((const float4*)bias)[lane];
        float ax, ay, az, aw;
        upk2(acc01, ax, ay); upk2(acc23, az, aw);
        ax = ax * inv + b4.x;
        ay = ay * inv + b4.y;
        az = az * inv + b4.z;
        aw = aw * inv + b4.w;
        ((float4*)(g_acc + (size_t)w * 128))[lane] = make_float4(ax, ay, az, aw);
        ps  = ax + ay + az + aw;
        ps2 = ax * ax + ay * ay + az * az + aw * aw;
    }
    ln_block_reduce(ps, ps2, slot);
}

// ---------------- LayerNorm apply (final layer only) ----------------
__global__ void k_ln_apply(const float* __restrict__ in,
                           const float* __restrict__ gm, const float* __restrict__ bt,
                           float* __restrict__ out, int slot) {
    int i = blockIdx.x * blockDim.x + threadIdx.x;
    if (i >= ND) return;
    double mu = g_red[2 * slot] * (1.0 / (double)ND);
    double var = g_red[2 * slot + 1] * (1.0 / (double)ND) - mu * mu;
    float inv = 1.0f / (sqrtf(fmaxf((float)var, 0.0f)) + EPSF);
    int c = i & 127;
    float v = in[i];
    out[i] = (v - (float)mu) * inv * gm[c] + bt[c];
}

// ---------------- launch ----------------
static inline int gridFor(long long n, int blk) { return (int)((n + blk - 1) / blk); }

extern "C" void kernel_launch(void* const* d_in, const int* in_sizes, int n_in,
                              void* d_out, int out_size) {
    const float* x   = (const float*)d_in[0];
    const int*   ei  = (const int*)d_in[1];
    const float* W0  = (const float*)d_in[2];
    const float* b0  = (const float*)d_in[3];
    const float* g0  = (const float*)d_in[4];
    const float* be0 = (const float*)d_in[5];
    const float* Wl1 = (const float*)d_in[6];
    const float* bl1 = (const float*)d_in[7];
    const float* Wr1 = (const float*)d_in[8];
    const float* br1 = (const float*)d_in[9];
    const float* att1= (const float*)d_in[10];
    const float* bg1 = (const float*)d_in[11];
    const float* g1  = (const float*)d_in[12];
    const float* be1 = (const float*)d_in[13];
    const float* W2  = (const float*)d_in[14];
    const float* b2  = (const float*)d_in[15];
    const float* g2  = (const float*)d_in[16];
    const float* be2 = (const float*)d_in[17];
    const float* Wl3 = (const float*)d_in[18];
    const float* bl3 = (const float*)d_in[19];
    const float* Wr3 = (const float*)d_in[20];
    const float* br3 = (const float*)d_in[21];
    const float* att3= (const float*)d_in[22];
    const float* bg3 = (const float*)d_in[23];
    const float* g3  = (const float*)d_in[24];
    const float* be3 = (const float*)d_in[25];
    float* out = (float*)d_out;

    const int* src = ei;
    const int* dst = ei + NE;

    const int BLK = 256;
    const int gE   = gridFor(NE, BLK);
    const int gND  = gridFor(ND, BLK);
    const int gNW  = gridFor((long long)NN * 32, BLK);
    const int nGemmX = gridFor(NN, 128);
    const dim3 gG1(nGemmX, 1), gG2(nGemmX, 2);
    const int nScanBlk = gridFor(NN, 1024);
    const int gInit = gridFor(6 * DD * DD, BLK);   // 98304 threads covers NN too
    const int gN256 = gridFor(NN, 256);

    __half* p_xwh; cudaGetSymbolAddress((void**)&p_xwh, g_xwh);
    __half* p_xlh; cudaGetSymbolAddress((void**)&p_xlh, g_xlh);
    float* p_xr;  cudaGetSymbolAddress((void**)&p_xr, g_xr);
    float* p_acc; cudaGetSymbolAddress((void**)&p_acc, g_acc);
    float* p_dinv; cudaGetSymbolAddress((void**)&p_dinv, g_dinv);
    __half* p_wh; cudaGetSymbolAddress((void**)&p_wh, g_wh);

    const __half* w0h  = p_wh;
    const __half* wl1h = p_wh + 1 * DD * DD;
    const __half* wr1h = p_wh + 2 * DD * DD;
    const __half* w2h  = p_wh + 3 * DD * DD;
    const __half* wl3h = p_wh + 4 * DD * DD;
    const __half* wr3h = p_wh + 5 * DD * DD;

    static bool attr_done = false;
    if (!attr_done) {
        cudaFuncSetAttribute(gemm128t<false, false>,
                             cudaFuncAttributeMaxDynamicSharedMemorySize, GEMM_SMEM);
        cudaFuncSetAttribute(gemm128t<true, false>,
                             cudaFuncAttributeMaxDynamicSharedMemorySize, GEMM_SMEM);
        cudaFuncSetAttribute(gemm128t<true, true>,
                             cudaFuncAttributeMaxDynamicSharedMemorySize, GEMM_SMEM);
        attr_done = true;
    }

    // ---- front (single stream): init -> hist -> scan1 -> gemm0 -> scan3 -> scatter
    k_init<<<gInit, BLK>>>(W0, Wl1, Wr1, W2, Wl3, Wr3);
    k_hist<<<gE, BLK>>>(dst);
    k_scan1<<<nScanBlk, 1024>>>();
    gemm128t<false, false><<<gG1, BLK, GEMM_SMEM>>>(x, w0h, nullptr, p_xwh,
                                                    nullptr, nullptr, nullptr, 0,
                                                    nullptr, nullptr, p_dinv);
    k_scan3<<<gN256, 256>>>(nScanBlk);
    k_scatter<<<gE, BLK>>>(src, dst);

    // ---- layer 0: GCN agg ----
    k_gcn_csr<<<gNW, BLK>>>(b0, 0);

    // ---- layer 1: GATv2 (H=8) ----
    gemm128t<true, true><<<gG2, BLK, GEMM_SMEM>>>(p_acc, wl1h, bl1, p_xlh,
                                                  wr1h, br1, p_xr, 0, g0, be0, nullptr);
    k_gat_csr<8><<<gNW, BLK>>>(att1, bg1, 1);

    // ---- layer 2: GCN ----
    gemm128t<true, false><<<gG1, BLK, GEMM_SMEM>>>(p_acc, w2h, nullptr, p_xwh,
                                                   nullptr, nullptr, nullptr, 1, g1, be1,
                                                   p_dinv);
    k_gcn_csr<<<gNW, BLK>>>(b2, 2);

    // ---- layer 3: GATv2 (H=1) ----
    gemm128t<true, true><<<gG2, BLK, GEMM_SMEM>>>(p_acc, wl3h, bl3, p_xlh,
                                                  wr3h, br3, p_xr, 2, g2, be2, nullptr);
    k_gat_csr<1><<<gNW, BLK>>>(att3, bg3, 3);

    // ---- final LN -> output ----
    k_ln_apply<<<gND, BLK>>>(p_acc, g3, be3, out, 3);
}

// round 14
// speedup vs baseline: 1.0426x; 1.0167x over previous
#include <cuda_runtime.h>
#include <cuda_fp16.h>
#include <mma.h>
#include <math.h>
#include <stdint.h>

using namespace nvcuda;

#define NN 50000
#define NE 800000
#define DD 128
#define ND (NN * DD)
#define EPSF 1e-5f
#define NEGS 0.2f

#define GEMM_SMEM 69632

// ---------------- scratch (static device globals; no allocation) ----------------
__device__ __half g_xwh[ND];    // GCN transform * dinv[row]  (half, gather payload)
__device__ __half g_xlh[ND];    // GAT left transform (half, gather payload)
__device__ __half g_xrh[ND];    // GAT right transform (half)
__device__ float g_acc[ND];     // aggregation output (bias added, pre-LN, fp32)
__device__ __half g_wh[6 * DD * DD];  // fp16 weight copies
__device__ float g_dinv[NN];    // deg^{-1/2}
__device__ int   g_cnt[NN];     // in-degree histogram (no self loop)
__device__ int   g_off[NN + 1]; // CSR offsets
__device__ int   g_cur[NN];     // scatter cursors
__device__ int   g_csrc[NE];    // CSR: src node per incoming edge
__device__ int   g_bsum[64];    // scan block totals
__device__ double g_red[8];     // (sum,sumsq) x 4 LN slots

typedef unsigned long long ull;

// ---------------- packed f32x2 helpers ----------------
__device__ __forceinline__ ull pk2(float a, float b) {
    ull r; asm("mov.b64 %0, {%1, %2};" : "=l"(r) : "f"(a), "f"(b)); return r;
}
__device__ __forceinline__ void upk2(ull p, float& a, float& b) {
    asm("mov.b64 {%0, %1}, %2;" : "=f"(a), "=f"(b) : "l"(p));
}
__device__ __forceinline__ ull fma2(ull a, ull b, ull c) {
    ull r; asm("fma.rn.f32x2 %0, %1, %2, %3;" : "=l"(r) : "l"(a), "l"(b), "l"(c)); return r;
}
__device__ __forceinline__ ull mul2p(ull a, ull b) {
    ull r; asm("mul.rn.f32x2 %0, %1, %2;" : "=l"(r) : "l"(a), "l"(b)); return r;
}
__device__ __forceinline__ ull add2p(ull a, ull b) {
    ull r; asm("add.rn.f32x2 %0, %1, %2;" : "=l"(r) : "l"(a), "l"(b)); return r;
}
__device__ __forceinline__ ull abs2p(ull a) {
    ull r; asm("and.b64 %0, %1, 0x7FFFFFFF7FFFFFFF;" : "=l"(r) : "l"(a)); return r;
}
__device__ __forceinline__ void h4_to_2x2(uint2 raw, ull& p01, ull& p23) {
    float2 a = __half22float2(*(__half2*)&raw.x);
    float2 b = __half22float2(*(__half2*)&raw.y);
    p01 = pk2(a.x, a.y); p23 = pk2(b.x, b.y);
}

// ---------------- fused init: zero hist + LN slots, convert weights ------------
__global__ void k_init(const float* __restrict__ w0, const float* __restrict__ w1,
                       const float* __restrict__ w2, const float* __restrict__ w3,
                       const float* __restrict__ w4, const float* __restrict__ w5) {
    int i = blockIdx.x * blockDim.x + threadIdx.x;
    if (i < NN) g_cnt[i] = 0;
    if (i < 8) g_red[i] = 0.0;
    if (i < 6 * DD * DD) {
        const float* ws[6] = {w0, w1, w2, w3, w4, w5};
        int m = i >> 14;
        int o = i & 16383;
        g_wh[i] = __float2half_rn(ws[m][o]);
    }
}
__global__ void k_hist(const int* __restrict__ dst) {
    int e = blockIdx.x * blockDim.x + threadIdx.x;
    if (e < NE) atomicAdd(&g_cnt[dst[e]], 1);
}
__global__ void k_scan1() {
    __shared__ int warp_sums[32];
    int tid = threadIdx.x;
    int lane = tid & 31, wid = tid >> 5;
    int i = blockIdx.x * 1024 + tid;
    int v = (i < NN) ? g_cnt[i] : 0;
    int x = v;
#pragma unroll
    for (int o = 1; o < 32; o <<= 1) {
        int y = __shfl_up_sync(0xffffffffu, x, o);
        if (lane >= o) x += y;
    }
    if (lane == 31) warp_sums[wid] = x;
    __syncthreads();
    if (wid == 0) {
        int ws = warp_sums[lane];
#pragma unroll
        for (int o = 1; o < 32; o <<= 1) {
            int y = __shfl_up_sync(0xffffffffu, ws, o);
            if (lane >= o) ws += y;
        }
        warp_sums[lane] = ws;
    }
    __syncthreads();
    int incl = x + (wid ? warp_sums[wid - 1] : 0);
    if (i < NN) {
        g_off[i] = incl - v;
        g_dinv[i] = rsqrtf((float)v + 1.0f);
    }
    if (tid == 1023) g_bsum[blockIdx.x] = incl;
}
__global__ void k_scan3(int nblk) {
    __shared__ int sb[64];
    __shared__ int prefix;
    int tid = threadIdx.x;
    if (tid < 64) sb[tid] = (tid < nblk) ? g_bsum[tid] : 0;
    __syncthreads();
    if (tid == 0) {
        int need = blockIdx.x >> 2;
        int s = 0;
        for (int k = 0; k < need; k++) s += sb[k];
        prefix = s;
    }
    __syncthreads();
    int i = blockIdx.x * 256 + tid;
    if (i < NN) {
        int o = g_off[i] + prefix;
        g_off[i] = o;
        g_cur[i] = o;
    }
    if (i == 0) g_off[NN] = NE;
}
__global__ void k_scatter(const int* __restrict__ src, const int* __restrict__ dst) {
    int e = blockIdx.x * blockDim.x + threadIdx.x;
    if (e >= NE) return;
    int pos = atomicAdd(&g_cur[dst[e]], 1);
    g_csrc[pos] = src[e];
}

// ---------------- tensor-core GEMM with fused input-LayerNorm+ReLU ----------------
// Both outputs half. rowscale applies to first (non-'second') output only.
template <bool LNIN, bool PAIR>
__global__ void __launch_bounds__(256, 3) gemm128t(
        const float* __restrict__ A,
        const __half* __restrict__ Wa16, const float* __restrict__ ba, __half* __restrict__ houta,
        const __half* __restrict__ Wb16, const float* __restrict__ bb, __half* __restrict__ houtb,
        int slot, const float* __restrict__ gm, const float* __restrict__ bt,
        const float* __restrict__ rowscale) {
    extern __shared__ char smem[];
    __half (*Ah)[136]  = (__half(*)[136])smem;
    __half (*Wsh)[136] = (__half(*)[136])(smem + 34816);

    bool second = PAIR && (blockIdx.y != 0);
    const __half* W16  = second ? Wb16 : Wa16;
    const float*  bias = second ? bb : ba;
    __half*       hout = second ? houtb : houta;

    int t = threadIdx.x;
    int row0 = blockIdx.x * 128;

    float fmu = 0.f, finv = 0.f;
    if (LNIN) {
        double mu = g_red[2 * slot] * (1.0 / (double)ND);
        double var = g_red[2 * slot + 1] * (1.0 / (double)ND) - mu * mu;
        fmu = (float)mu;
        finv = 1.0f / (sqrtf(fmaxf((float)var, 0.0f)) + EPSF);
    }

#pragma unroll
    for (int j = 0; j < 8; j++) {
        int u = t + j * 256;
        int lin = u * 8;
        int r = lin >> 7, c = lin & 127;
        *(uint4*)&Wsh[r][c] = *(const uint4*)(W16 + (size_t)r * 128 + c);
    }
#pragma unroll
    for (int j = 0; j < 16; j++) {
        int f = t + j * 256;
        int lin = f * 4;
        int r = lin >> 7, c = lin & 127;
        int gr = row0 + r;
        float4 v = (gr < NN) ? *(const float4*)(A + (size_t)gr * 128 + c)
                             : make_float4(0.f, 0.f, 0.f, 0.f);
        if (LNIN) {
            float4 gv = *(const float4*)(gm + c);
            float4 bv = *(const float4*)(bt + c);
            v.x = fmaxf((v.x - fmu) * finv * gv.x + bv.x, 0.f);
            v.y = fmaxf((v.y - fmu) * finv * gv.y + bv.y, 0.f);
            v.z = fmaxf((v.z - fmu) * finv * gv.z + bv.z, 0.f);
            v.w = fmaxf((v.w - fmu) * finv * gv.w + bv.w, 0.f);
        }
        __half2* dsth = (__half2*)&Ah[r][c];
        dsth[0] = __floats2half2_rn(v.x, v.y);
        dsth[1] = __floats2half2_rn(v.z, v.w);
    }
    __syncthreads();

    int w = t >> 5;
    int lane = t & 31;

    wmma::fragment<wmma::accumulator, 16, 16, 16, float> acc[8];
#pragma unroll
    for (int n = 0; n < 8; n++) wmma::fill_fragment(acc[n], 0.0f);

#pragma unroll
    for (int k = 0; k < 8; k++) {
        wmma::fragment<wmma::matrix_a, 16, 16, 16, __half, wmma::row_major> af;
        wmma::load_matrix_sync(af, &Ah[w * 16][k * 16], 136);
#pragma unroll
        for (int n = 0; n < 8; n++) {
            wmma::fragment<wmma::matrix_b, 16, 16, 16, __half, wmma::row_major> bf;
            wmma::load_matrix_sync(bf, &Wsh[k * 16][n * 16], 136);
            wmma::mma_sync(acc[n], af, bf, acc[n]);
        }
    }
    __syncthreads();

    float* stage = (float*)smem + (size_t)w * (16 * 136);
#pragma unroll
    for (int n = 0; n < 8; n++)
        wmma::store_matrix_sync(stage + n * 16, acc[n], 136, wmma::mem_row_major);
    __syncwarp();

    int row_in = lane >> 1;
    int c0 = (lane & 1) * 64;
    int gr = row0 + w * 16 + row_in;
    if (gr < NN) {
        float sc = (!second && rowscale) ? rowscale[gr] : 1.0f;
#pragma unroll
        for (int q = 0; q < 64; q += 8) {
            int colg = c0 + q;
            float4 v0 = *(float4*)(stage + row_in * 136 + colg);
            float4 v1 = *(float4*)(stage + row_in * 136 + colg + 4);
            if (bias) {
                float4 b0 = *(const float4*)(bias + colg);
                float4 b1 = *(const float4*)(bias + colg + 4);
                v0.x += b0.x; v0.y += b0.y; v0.z += b0.z; v0.w += b0.w;
                v1.x += b1.x; v1.y += b1.y; v1.z += b1.z; v1.w += b1.w;
            }
            __half2 hh[4];
            hh[0] = __floats2half2_rn(v0.x * sc, v0.y * sc);
            hh[1] = __floats2half2_rn(v0.z * sc, v0.w * sc);
            hh[2] = __floats2half2_rn(v1.x * sc, v1.y * sc);
            hh[3] = __floats2half2_rn(v1.z * sc, v1.w * sc);
            *(uint4*)(hout + (size_t)gr * 128 + colg) = *(uint4*)hh;
        }
    }
}

// ---------------- block epilogue: fused LN partial reduction ----------------
__device__ __forceinline__ void ln_block_reduce(float s, float s2, int slot) {
#pragma unroll
    for (int o = 16; o; o >>= 1) {
        s  += __shfl_xor_sync(0xffffffffu, s, o);
        s2 += __shfl_xor_sync(0xffffffffu, s2, o);
    }
    __shared__ float shs[8], shs2[8];
    int wid = threadIdx.x >> 5, lane = threadIdx.x & 31;
    if (lane == 0) { shs[wid] = s; shs2[wid] = s2; }
    __syncthreads();
    if (threadIdx.x == 0) {
        double ts = 0.0, t2 = 0.0;
        int nw = blockDim.x >> 5;
        for (int k = 0; k < nw; k++) { ts += (double)shs[k]; t2 += (double)shs2[k]; }
        atomicAdd(&g_red[2 * slot], ts);
        atomicAdd(&g_red[2 * slot + 1], t2);
    }
}

// ---------------- GCN aggregation (prescaled payload: pure sum, chunk-8) --------
__global__ void __launch_bounds__(256) k_gcn_csr(const float* __restrict__ bias, int slot) {
    int w = (blockIdx.x * blockDim.x + threadIdx.x) >> 5;
    int lane = threadIdx.x & 31;
    float s = 0.f, s2 = 0.f;
    if (w < NN) {
        float dd = g_dinv[w];
        uint2 rawS = *(const uint2*)(g_xwh + (size_t)w * 128 + lane * 4);
        ull a01, a23;
        h4_to_2x2(rawS, a01, a23);          // self payload (already * dinv[self])
        int b = g_off[w], e = g_off[w + 1];
        int i = b;
        for (; i + 8 <= e; i += 8) {
            int si[8];
#pragma unroll
            for (int j = 0; j < 8; j++) si[j] = g_csrc[i + j];
            uint2 raw[8];
#pragma unroll
            for (int j = 0; j < 8; j++)
                raw[j] = *(const uint2*)(g_xwh + (size_t)si[j] * 128 + lane * 4);
#pragma unroll
            for (int j = 0; j < 8; j++) {
                ull u01, u23;
                h4_to_2x2(raw[j], u01, u23);
                a01 = add2p(a01, u01);
                a23 = add2p(a23, u23);
            }
        }
        for (; i < e; i++) {
            uint2 rw = *(const uint2*)(g_xwh + (size_t)g_csrc[i] * 128 + lane * 4);
            ull u01, u23; h4_to_2x2(rw, u01, u23);
            a01 = add2p(a01, u01); a23 = add2p(a23, u23);
        }
        float4 b4 = ((const float4*)bias)[lane];
        float ax, ay, az, aw;
        upk2(a01, ax, ay); upk2(a23, az, aw);
        ax = ax * dd + b4.x; ay = ay * dd + b4.y;
        az = az * dd + b4.z; aw = aw * dd + b4.w;
        ((float4*)(g_acc + (size_t)w * 128))[lane] = make_float4(ax, ay, az, aw);
        s  = ax + ay + az + aw;
        s2 = ax * ax + ay * ay + az * az + aw * aw;
    }
    ln_block_reduce(s, s2, slot);
}

// ---------------- fused GATv2 (CSR gather + online softmax, chunk-4) ------------
#define C06 0x3F19999A3F19999AULL
#define C04 0x3ECCCCCD3ECCCCCDULL

template <int H>
__device__ __forceinline__ float score2(ull l01, ull l23, ull r01, ull r23,
                                        ull a01, ull a23) {
    ull s01 = add2p(l01, r01), s23 = add2p(l23, r23);
    ull b01 = abs2p(s01),      b23 = abs2p(s23);
    ull t01 = fma2(b01, C04, mul2p(s01, C06));
    ull t23 = fma2(b23, C04, mul2p(s23, C06));
    ull qp  = fma2(t23, a23, mul2p(t01, a01));
    float qa, qb;
    upk2(qp, qa, qb);
    float q = qa + qb;
    if (H == 8) {
        q += __shfl_xor_sync(0xffffffffu, q, 1);
        q += __shfl_xor_sync(0xffffffffu, q, 2);
    } else {
#pragma unroll
        for (int o = 16; o; o >>= 1) q += __shfl_xor_sync(0xffffffffu, q, o);
    }
    return q;
}

template <int H>
__global__ void __launch_bounds__(256) k_gat_csr(const float* __restrict__ att,
                                                 const float* __restrict__ bias, int slot) {
    int w = (blockIdx.x * blockDim.x + threadIdx.x) >> 5;
    int lane = threadIdx.x & 31;
    float ps = 0.f, ps2 = 0.f;
    if (w < NN) {
        uint2 rraw = *(const uint2*)(g_xrh + (size_t)w * 128 + lane * 4);
        ull r01, r23;
        h4_to_2x2(rraw, r01, r23);
        float4 a4 = ((const float4*)att)[lane];
        ull a01 = pk2(a4.x, a4.y), a23 = pk2(a4.z, a4.w);

        uint2 rawl = *(const uint2*)(g_xlh + (size_t)w * 128 + lane * 4);
        ull l01, l23;
        h4_to_2x2(rawl, l01, l23);
        float m = score2<H>(l01, l23, r01, r23, a01, a23);
        float den = 1.0f;
        ull acc01 = l01, acc23 = l23;

        int b = g_off[w], e = g_off[w + 1];
        int i = b;
        for (; i + 4 <= e; i += 4) {
            int s0 = g_csrc[i], s1 = g_csrc[i + 1], s2 = g_csrc[i + 2], s3 = g_csrc[i + 3];
            uint2 w0r = *(const uint2*)(g_xlh + (size_t)s0 * 128 + lane * 4);
            uint2 w1r = *(const uint2*)(g_xlh + (size_t)s1 * 128 + lane * 4);
            uint2 w2r = *(const uint2*)(g_xlh + (size_t)s2 * 128 + lane * 4);
            uint2 w3r = *(const uint2*)(g_xlh + (size_t)s3 * 128 + lane * 4);
            ull u0a, u0b, u1a, u1b, u2a, u2b, u3a, u3b;
            h4_to_2x2(w0r, u0a, u0b);
            h4_to_2x2(w1r, u1a, u1b);
            h4_to_2x2(w2r, u2a, u2b);
            h4_to_2x2(w3r, u3a, u3b);
            float q0 = score2<H>(u0a, u0b, r01, r23, a01, a23);
            float q1 = score2<H>(u1a, u1b, r01, r23, a01, a23);
            float q2 = score2<H>(u2a, u2b, r01, r23, a01, a23);
            float q3 = score2<H>(u3a, u3b, r01, r23, a01, a23);
            float nm = fmaxf(fmaxf(fmaxf(q0, q1), fmaxf(q2, q3)), m);
            float so = __expf(m - nm);
            float w0 = __expf(q0 - nm), w1 = __expf(q1 - nm);
            float w2 = __expf(q2 - nm), w3 = __expf(q3 - nm);
            den = den * so + w0 + w1 + w2 + w3;
            ull so2 = pk2(so, so);
            ull w0p = pk2(w0, w0), w1p = pk2(w1, w1);
            ull w2p = pk2(w2, w2), w3p = pk2(w3, w3);
            acc01 = mul2p(acc01, so2);
            acc01 = fma2(u0a, w0p, acc01);
            acc01 = fma2(u1a, w1p, acc01);
            acc01 = fma2(u2a, w2p, acc01);
            acc01 = fma2(u3a, w3p, acc01);
            acc23 = mul2p(acc23, so2);
            acc23 = fma2(u0b, w0p, acc23);
            acc23 = fma2(u1b, w1p, acc23);
            acc23 = fma2(u2b, w2p, acc23);
            acc23 = fma2(u3b, w3p, acc23);
            m = nm;
        }
        for (; i < e; i++) {
            uint2 vr = *(const uint2*)(g_xlh + (size_t)g_csrc[i] * 128 + lane * 4);
            ull ua, ub; h4_to_2x2(vr, ua, ub);
            float q = score2<H>(ua, ub, r01, r23, a01, a23);
            float nm = fmaxf(m, q);
            float so = __expf(m - nm), wg = __expf(q - nm);
            den = den * so + wg;
            ull so2 = pk2(so, so), wg2 = pk2(wg, wg);
            acc01 = fma2(ua, wg2, mul2p(acc01, so2));
            acc23 = fma2(ub, wg2, mul2p(acc23, so2));
            m = nm;
        }
        float inv = 1.0f / den;
        float4 b4 = ((const float4*)bias)[lane];
        float ax, ay, az, aw;
        upk2(acc01, ax, ay); upk2(acc23, az, aw);
        ax = ax * inv + b4.x;
        ay = ay * inv + b4.y;
        az = az * inv + b4.z;
        aw = aw * inv + b4.w;
        ((float4*)(g_acc + (size_t)w * 128))[lane] = make_float4(ax, ay, az, aw);
        ps  = ax + ay + az + aw;
        ps2 = ax * ax + ay * ay + az * az + aw * aw;
    }
    ln_block_reduce(ps, ps2, slot);
}

// ---------------- LayerNorm apply (final layer only) ----------------
__global__ void k_ln_apply(const float* __restrict__ in,
                           const float* __restrict__ gm, const float* __restrict__ bt,
                           float* __restrict__ out, int slot) {
    int i = blockIdx.x * blockDim.x + threadIdx.x;
    if (i >= ND) return;
    double mu = g_red[2 * slot] * (1.0 / (double)ND);
    double var = g_red[2 * slot + 1] * (1.0 / (double)ND) - mu * mu;
    float inv = 1.0f / (sqrtf(fmaxf((float)var, 0.0f)) + EPSF);
    int c = i & 127;
    float v = in[i];
    out[i] = (v - (float)mu) * inv * gm[c] + bt[c];
}

// ---------------- launch ----------------
static inline int gridFor(long long n, int blk) { return (int)((n + blk - 1) / blk); }

extern "C" void kernel_launch(void* const* d_in, const int* in_sizes, int n_in,
                              void* d_out, int out_size) {
    const float* x   = (const float*)d_in[0];
    const int*   ei  = (const int*)d_in[1];
    const float* W0  = (const float*)d_in[2];
    const float* b0  = (const float*)d_in[3];
    const float* g0  = (const float*)d_in[4];
    const float* be0 = (const float*)d_in[5];
    const float* Wl1 = (const float*)d_in[6];
    const float* bl1 = (const float*)d_in[7];
    const float* Wr1 = (const float*)d_in[8];
    const float* br1 = (const float*)d_in[9];
    const float* att1= (const float*)d_in[10];
    const float* bg1 = (const float*)d_in[11];
    const float* g1  = (const float*)d_in[12];
    const float* be1 = (const float*)d_in[13];
    const float* W2  = (const float*)d_in[14];
    const float* b2  = (const float*)d_in[15];
    const float* g2  = (const float*)d_in[16];
    const float* be2 = (const float*)d_in[17];
    const float* Wl3 = (const float*)d_in[18];
    const float* bl3 = (const float*)d_in[19];
    const float* Wr3 = (const float*)d_in[20];
    const float* br3 = (const float*)d_in[21];
    const float* att3= (const float*)d_in[22];
    const float* bg3 = (const float*)d_in[23];
    const float* g3  = (const float*)d_in[24];
    const float* be3 = (const float*)d_in[25];
    float* out = (float*)d_out;

    const int* src = ei;
    const int* dst = ei + NE;

    const int BLK = 256;
    const int gE   = gridFor(NE, BLK);
    const int gND  = gridFor(ND, BLK);
    const int gNW  = gridFor((long long)NN * 32, BLK);
    const int nGemmX = gridFor(NN, 128);
    const dim3 gG1(nGemmX, 1), gG2(nGemmX, 2);
    const int nScanBlk = gridFor(NN, 1024);
    const int gInit = gridFor(6 * DD * DD, BLK);
    const int gN256 = gridFor(NN, 256);

    __half* p_xwh; cudaGetSymbolAddress((void**)&p_xwh, g_xwh);
    __half* p_xlh; cudaGetSymbolAddress((void**)&p_xlh, g_xlh);
    __half* p_xrh; cudaGetSymbolAddress((void**)&p_xrh, g_xrh);
    float* p_acc; cudaGetSymbolAddress((void**)&p_acc, g_acc);
    float* p_dinv; cudaGetSymbolAddress((void**)&p_dinv, g_dinv);
    __half* p_wh; cudaGetSymbolAddress((void**)&p_wh, g_wh);

    const __half* w0h  = p_wh;
    const __half* wl1h = p_wh + 1 * DD * DD;
    const __half* wr1h = p_wh + 2 * DD * DD;
    const __half* w2h  = p_wh + 3 * DD * DD;
    const __half* wl3h = p_wh + 4 * DD * DD;
    const __half* wr3h = p_wh + 5 * DD * DD;

    static bool attr_done = false;
    if (!attr_done) {
        cudaFuncSetAttribute(gemm128t<false, false>,
                             cudaFuncAttributeMaxDynamicSharedMemorySize, GEMM_SMEM);
        cudaFuncSetAttribute(gemm128t<true, false>,
                             cudaFuncAttributeMaxDynamicSharedMemorySize, GEMM_SMEM);
        cudaFuncSetAttribute(gemm128t<true, true>,
                             cudaFuncAttributeMaxDynamicSharedMemorySize, GEMM_SMEM);
        attr_done = true;
    }

    // ---- front: init -> hist -> scan1 -> gemm0 -> scan3 -> scatter
    k_init<<<gInit, BLK>>>(W0, Wl1, Wr1, W2, Wl3, Wr3);
    k_hist<<<gE, BLK>>>(dst);
    k_scan1<<<nScanBlk, 1024>>>();
    gemm128t<false, false><<<gG1, BLK, GEMM_SMEM>>>(x, w0h, nullptr, p_xwh,
                                                    nullptr, nullptr, nullptr, 0,
                                                    nullptr, nullptr, p_dinv);
    k_scan3<<<gN256, 256>>>(nScanBlk);
    k_scatter<<<gE, BLK>>>(src, dst);

    // ---- layer 0: GCN agg ----
    k_gcn_csr<<<gNW, BLK>>>(b0, 0);

    // ---- layer 1: GATv2 (H=8) ----
    gemm128t<true, true><<<gG2, BLK, GEMM_SMEM>>>(p_acc, wl1h, bl1, p_xlh,
                                                  wr1h, br1, p_xrh, 0, g0, be0, nullptr);
    k_gat_csr<8><<<gNW, BLK>>>(att1, bg1, 1);

    // ---- layer 2: GCN ----
    gemm128t<true, false><<<gG1, BLK, GEMM_SMEM>>>(p_acc, w2h, nullptr, p_xwh,
                                                   nullptr, nullptr, nullptr, 1, g1, be1,
                                                   p_dinv);
    k_gcn_csr<<<gNW, BLK>>>(b2, 2);

    // ---- layer 3: GATv2 (H=1) ----
    gemm128t<true, true><<<gG2, BLK, GEMM_SMEM>>>(p_acc, wl3h, bl3, p_xlh,
                                                  wr3h, br3, p_xrh, 2, g2, be2, nullptr);
    k_gat_csr<1><<<gNW, BLK>>>(att3, bg3, 3);

    // ---- final LN -> output ----
    k_ln_apply<<<gND, BLK>>>(p_acc, g3, be3, out, 3);
}

// round 15
// speedup vs baseline: 1.1020x; 1.0570x over previous
#include <cuda_runtime.h>
#include <cuda_fp16.h>
#include <mma.h>
#include <math.h>
#include <stdint.h>

using namespace nvcuda;

#define NN 50000
#define NE 800000
#define DD 128
#define ND (NN * DD)
#define EPSF 1e-5f
#define NEGS 0.2f

#define GEMM_SMEM 69632

// ---------------- scratch (static device globals; no allocation) ----------------
__device__ __half g_xwh[ND];    // GCN transform * dinv[row]  (half, gather payload)
__device__ __half g_xlh[ND];    // GAT left transform (half, gather payload)
__device__ __half g_xrh[ND];    // GAT right transform (half)
__device__ __half g_acch[ND];   // aggregation output (bias added, pre-LN, HALF)
__device__ __half g_wh[6 * DD * DD];  // fp16 weight copies
__device__ float g_dinv[NN];    // deg^{-1/2}
__device__ int   g_cnt[NN];     // in-degree histogram (no self loop)
__device__ int   g_off[NN + 1]; // CSR offsets
__device__ int   g_cur[NN];     // scatter cursors
__device__ int   g_csrc[NE];    // CSR: src node per incoming edge
__device__ int   g_bsum[64];    // scan block totals
__device__ double g_red[8];     // (sum,sumsq) x 4 LN slots

typedef unsigned long long ull;

// ---------------- packed f32x2 helpers ----------------
__device__ __forceinline__ ull pk2(float a, float b) {
    ull r; asm("mov.b64 %0, {%1, %2};" : "=l"(r) : "f"(a), "f"(b)); return r;
}
__device__ __forceinline__ void upk2(ull p, float& a, float& b) {
    asm("mov.b64 {%0, %1}, %2;" : "=f"(a), "=f"(b) : "l"(p));
}
__device__ __forceinline__ ull fma2(ull a, ull b, ull c) {
    ull r; asm("fma.rn.f32x2 %0, %1, %2, %3;" : "=l"(r) : "l"(a), "l"(b), "l"(c)); return r;
}
__device__ __forceinline__ ull mul2p(ull a, ull b) {
    ull r; asm("mul.rn.f32x2 %0, %1, %2;" : "=l"(r) : "l"(a), "l"(b)); return r;
}
__device__ __forceinline__ ull add2p(ull a, ull b) {
    ull r; asm("add.rn.f32x2 %0, %1, %2;" : "=l"(r) : "l"(a), "l"(b)); return r;
}
__device__ __forceinline__ ull abs2p(ull a) {
    ull r; asm("and.b64 %0, %1, 0x7FFFFFFF7FFFFFFF;" : "=l"(r) : "l"(a)); return r;
}
__device__ __forceinline__ void h4_to_2x2(uint2 raw, ull& p01, ull& p23) {
    float2 a = __half22float2(*(__half2*)&raw.x);
    float2 b = __half22float2(*(__half2*)&raw.y);
    p01 = pk2(a.x, a.y); p23 = pk2(b.x, b.y);
}

// ---------------- fused init ----------------
__global__ void k_init(const float* __restrict__ w0, const float* __restrict__ w1,
                       const float* __restrict__ w2, const float* __restrict__ w3,
                       const float* __restrict__ w4, const float* __restrict__ w5) {
    int i = blockIdx.x * blockDim.x + threadIdx.x;
    if (i < NN) g_cnt[i] = 0;
    if (i < 8) g_red[i] = 0.0;
    if (i < 6 * DD * DD) {
        const float* ws[6] = {w0, w1, w2, w3, w4, w5};
        int m = i >> 14;
        int o = i & 16383;
        g_wh[i] = __float2half_rn(ws[m][o]);
    }
}
__global__ void k_hist(const int* __restrict__ dst) {
    int e = blockIdx.x * blockDim.x + threadIdx.x;
    if (e < NE) atomicAdd(&g_cnt[dst[e]], 1);
}
__global__ void k_scan1() {
    __shared__ int warp_sums[32];
    int tid = threadIdx.x;
    int lane = tid & 31, wid = tid >> 5;
    int i = blockIdx.x * 1024 + tid;
    int v = (i < NN) ? g_cnt[i] : 0;
    int x = v;
#pragma unroll
    for (int o = 1; o < 32; o <<= 1) {
        int y = __shfl_up_sync(0xffffffffu, x, o);
        if (lane >= o) x += y;
    }
    if (lane == 31) warp_sums[wid] = x;
    __syncthreads();
    if (wid == 0) {
        int ws = warp_sums[lane];
#pragma unroll
        for (int o = 1; o < 32; o <<= 1) {
            int y = __shfl_up_sync(0xffffffffu, ws, o);
            if (lane >= o) ws += y;
        }
        warp_sums[lane] = ws;
    }
    __syncthreads();
    int incl = x + (wid ? warp_sums[wid - 1] : 0);
    if (i < NN) {
        g_off[i] = incl - v;
        g_dinv[i] = rsqrtf((float)v + 1.0f);
    }
    if (tid == 1023) g_bsum[blockIdx.x] = incl;
}
__global__ void k_scan3(int nblk) {
    __shared__ int sb[64];
    __shared__ int prefix;
    int tid = threadIdx.x;
    if (tid < 64) sb[tid] = (tid < nblk) ? g_bsum[tid] : 0;
    __syncthreads();
    if (tid == 0) {
        int need = blockIdx.x >> 2;
        int s = 0;
        for (int k = 0; k < need; k++) s += sb[k];
        prefix = s;
    }
    __syncthreads();
    int i = blockIdx.x * 256 + tid;
    if (i < NN) {
        int o = g_off[i] + prefix;
        g_off[i] = o;
        g_cur[i] = o;
    }
    if (i == 0) g_off[NN] = NE;
}
__global__ void k_scatter(const int* __restrict__ src, const int* __restrict__ dst) {
    int e = blockIdx.x * blockDim.x + threadIdx.x;
    if (e >= NE) return;
    int pos = atomicAdd(&g_cur[dst[e]], 1);
    g_csrc[pos] = src[e];
}

// ---------------- tensor-core GEMM with fused input-LayerNorm+ReLU ----------------
// LNIN=true: A is HALF (g_acch), LN+ReLU applied while staging.
// LNIN=false: A is FLOAT (external x).
// Both outputs half. rowscale applies to first output only.
template <bool LNIN, bool PAIR>
__global__ void __launch_bounds__(256, 3) gemm128t(
        const void* __restrict__ Araw,
        const __half* __restrict__ Wa16, const float* __restrict__ ba, __half* __restrict__ houta,
        const __half* __restrict__ Wb16, const float* __restrict__ bb, __half* __restrict__ houtb,
        int slot, const float* __restrict__ gm, const float* __restrict__ bt,
        const float* __restrict__ rowscale) {
    extern __shared__ char smem[];
    __half (*Ah)[136]  = (__half(*)[136])smem;
    __half (*Wsh)[136] = (__half(*)[136])(smem + 34816);

    bool second = PAIR && (blockIdx.y != 0);
    const __half* W16  = second ? Wb16 : Wa16;
    const float*  bias = second ? bb : ba;
    __half*       hout = second ? houtb : houta;

    int t = threadIdx.x;
    int row0 = blockIdx.x * 128;

    float fmu = 0.f, finv = 0.f;
    if (LNIN) {
        double mu = g_red[2 * slot] * (1.0 / (double)ND);
        double var = g_red[2 * slot + 1] * (1.0 / (double)ND) - mu * mu;
        fmu = (float)mu;
        finv = 1.0f / (sqrtf(fmaxf((float)var, 0.0f)) + EPSF);
    }

#pragma unroll
    for (int j = 0; j < 8; j++) {
        int u = t + j * 256;
        int lin = u * 8;
        int r = lin >> 7, c = lin & 127;
        *(uint4*)&Wsh[r][c] = *(const uint4*)(W16 + (size_t)r * 128 + c);
    }
    if (LNIN) {
        const __half* A = (const __half*)Araw;
        // 128x128 halfs = 2048 uint4; 8 per thread
#pragma unroll
        for (int j = 0; j < 8; j++) {
            int u = t + j * 256;
            int lin = u * 8;
            int r = lin >> 7, c = lin & 127;
            int gr = row0 + r;
            uint4 raw = make_uint4(0u, 0u, 0u, 0u);
            if (gr < NN) raw = *(const uint4*)(A + (size_t)gr * 128 + c);
            float2 f0 = __half22float2(*(__half2*)&raw.x);
            float2 f1 = __half22float2(*(__half2*)&raw.y);
            float2 f2 = __half22float2(*(__half2*)&raw.z);
            float2 f3 = __half22float2(*(__half2*)&raw.w);
            float4 g0v = *(const float4*)(gm + c);
            float4 g1v = *(const float4*)(gm + c + 4);
            float4 b0v = *(const float4*)(bt + c);
            float4 b1v = *(const float4*)(bt + c + 4);
            f0.x = fmaxf((f0.x - fmu) * finv * g0v.x + b0v.x, 0.f);
            f0.y = fmaxf((f0.y - fmu) * finv * g0v.y + b0v.y, 0.f);
            f1.x = fmaxf((f1.x - fmu) * finv * g0v.z + b0v.z, 0.f);
            f1.y = fmaxf((f1.y - fmu) * finv * g0v.w + b0v.w, 0.f);
            f2.x = fmaxf((f2.x - fmu) * finv * g1v.x + b1v.x, 0.f);
            f2.y = fmaxf((f2.y - fmu) * finv * g1v.y + b1v.y, 0.f);
            f3.x = fmaxf((f3.x - fmu) * finv * g1v.z + b1v.z, 0.f);
            f3.y = fmaxf((f3.y - fmu) * finv * g1v.w + b1v.w, 0.f);
            __half2 hh[4];
            hh[0] = __floats2half2_rn(f0.x, f0.y);
            hh[1] = __floats2half2_rn(f1.x, f1.y);
            hh[2] = __floats2half2_rn(f2.x, f2.y);
            hh[3] = __floats2half2_rn(f3.x, f3.y);
            *(uint4*)&Ah[r][c] = *(uint4*)hh;
        }
    } else {
        const float* A = (const float*)Araw;
#pragma unroll
        for (int j = 0; j < 16; j++) {
            int f = t + j * 256;
            int lin = f * 4;
            int r = lin >> 7, c = lin & 127;
            int gr = row0 + r;
            float4 v = (gr < NN) ? *(const float4*)(A + (size_t)gr * 128 + c)
                                 : make_float4(0.f, 0.f, 0.f, 0.f);
            __half2* dsth = (__half2*)&Ah[r][c];
            dsth[0] = __floats2half2_rn(v.x, v.y);
            dsth[1] = __floats2half2_rn(v.z, v.w);
        }
    }
    __syncthreads();

    int w = t >> 5;
    int lane = t & 31;

    wmma::fragment<wmma::accumulator, 16, 16, 16, float> acc[8];
#pragma unroll
    for (int n = 0; n < 8; n++) wmma::fill_fragment(acc[n], 0.0f);

#pragma unroll
    for (int k = 0; k < 8; k++) {
        wmma::fragment<wmma::matrix_a, 16, 16, 16, __half, wmma::row_major> af;
        wmma::load_matrix_sync(af, &Ah[w * 16][k * 16], 136);
#pragma unroll
        for (int n = 0; n < 8; n++) {
            wmma::fragment<wmma::matrix_b, 16, 16, 16, __half, wmma::row_major> bf;
            wmma::load_matrix_sync(bf, &Wsh[k * 16][n * 16], 136);
            wmma::mma_sync(acc[n], af, bf, acc[n]);
        }
    }
    __syncthreads();

    float* stage = (float*)smem + (size_t)w * (16 * 136);
#pragma unroll
    for (int n = 0; n < 8; n++)
        wmma::store_matrix_sync(stage + n * 16, acc[n], 136, wmma::mem_row_major);
    __syncwarp();

    int row_in = lane >> 1;
    int c0 = (lane & 1) * 64;
    int gr = row0 + w * 16 + row_in;
    if (gr < NN) {
        float sc = (!second && rowscale) ? rowscale[gr] : 1.0f;
#pragma unroll
        for (int q = 0; q < 64; q += 8) {
            int colg = c0 + q;
            float4 v0 = *(float4*)(stage + row_in * 136 + colg);
            float4 v1 = *(float4*)(stage + row_in * 136 + colg + 4);
            if (bias) {
                float4 b0 = *(const float4*)(bias + colg);
                float4 b1 = *(const float4*)(bias + colg + 4);
                v0.x += b0.x; v0.y += b0.y; v0.z += b0.z; v0.w += b0.w;
                v1.x += b1.x; v1.y += b1.y; v1.z += b1.z; v1.w += b1.w;
            }
            __half2 hh[4];
            hh[0] = __floats2half2_rn(v0.x * sc, v0.y * sc);
            hh[1] = __floats2half2_rn(v0.z * sc, v0.w * sc);
            hh[2] = __floats2half2_rn(v1.x * sc, v1.y * sc);
            hh[3] = __floats2half2_rn(v1.z * sc, v1.w * sc);
            *(uint4*)(hout + (size_t)gr * 128 + colg) = *(uint4*)hh;
        }
    }
}

// ---------------- block epilogue: fused LN partial reduction ----------------
__device__ __forceinline__ void ln_block_reduce(float s, float s2, int slot) {
#pragma unroll
    for (int o = 16; o; o >>= 1) {
        s  += __shfl_xor_sync(0xffffffffu, s, o);
        s2 += __shfl_xor_sync(0xffffffffu, s2, o);
    }
    __shared__ float shs[8], shs2[8];
    int wid = threadIdx.x >> 5, lane = threadIdx.x & 31;
    if (lane == 0) { shs[wid] = s; shs2[wid] = s2; }
    __syncthreads();
    if (threadIdx.x == 0) {
        double ts = 0.0, t2 = 0.0;
        int nw = blockDim.x >> 5;
        for (int k = 0; k < nw; k++) { ts += (double)shs[k]; t2 += (double)shs2[k]; }
        atomicAdd(&g_red[2 * slot], ts);
        atomicAdd(&g_red[2 * slot + 1], t2);
    }
}

__device__ __forceinline__ void store_acc_half(int w, int lane,
                                               float ax, float ay, float az, float aw) {
    uint2 st;
    *(__half2*)&st.x = __floats2half2_rn(ax, ay);
    *(__half2*)&st.y = __floats2half2_rn(az, aw);
    *(uint2*)(g_acch + (size_t)w * 128 + lane * 4) = st;
}

// ---------------- GCN aggregation (prescaled payload: pure sum, chunk-8) --------
__global__ void __launch_bounds__(256) k_gcn_csr(const float* __restrict__ bias, int slot) {
    int w = (blockIdx.x * blockDim.x + threadIdx.x) >> 5;
    int lane = threadIdx.x & 31;
    float s = 0.f, s2 = 0.f;
    if (w < NN) {
        float dd = g_dinv[w];
        uint2 rawS = *(const uint2*)(g_xwh + (size_t)w * 128 + lane * 4);
        ull a01, a23;
        h4_to_2x2(rawS, a01, a23);
        int b = g_off[w], e = g_off[w + 1];
        int i = b;
        for (; i + 8 <= e; i += 8) {
            int si[8];
#pragma unroll
            for (int j = 0; j < 8; j++) si[j] = g_csrc[i + j];
            uint2 raw[8];
#pragma unroll
            for (int j = 0; j < 8; j++)
                raw[j] = *(const uint2*)(g_xwh + (size_t)si[j] * 128 + lane * 4);
#pragma unroll
            for (int j = 0; j < 8; j++) {
                ull u01, u23;
                h4_to_2x2(raw[j], u01, u23);
                a01 = add2p(a01, u01);
                a23 = add2p(a23, u23);
            }
        }
        for (; i < e; i++) {
            uint2 rw = *(const uint2*)(g_xwh + (size_t)g_csrc[i] * 128 + lane * 4);
            ull u01, u23; h4_to_2x2(rw, u01, u23);
            a01 = add2p(a01, u01); a23 = add2p(a23, u23);
        }
        float4 b4 = ((const float4*)bias)[lane];
        float ax, ay, az, aw;
        upk2(a01, ax, ay); upk2(a23, az, aw);
        ax = ax * dd + b4.x; ay = ay * dd + b4.y;
        az = az * dd + b4.z; aw = aw * dd + b4.w;
        store_acc_half(w, lane, ax, ay, az, aw);
        s  = ax + ay + az + aw;
        s2 = ax * ax + ay * ay + az * az + aw * aw;
    }
    ln_block_reduce(s, s2, slot);
}

// ---------------- fused GATv2 (CSR gather + online softmax, chunk-4) ------------
#define C06 0x3F19999A3F19999AULL
#define C04 0x3ECCCCCD3ECCCCCDULL

template <int H>
__device__ __forceinline__ float score2(ull l01, ull l23, ull r01, ull r23,
                                        ull a01, ull a23) {
    ull s01 = add2p(l01, r01), s23 = add2p(l23, r23);
    ull b01 = abs2p(s01),      b23 = abs2p(s23);
    ull t01 = fma2(b01, C04, mul2p(s01, C06));
    ull t23 = fma2(b23, C04, mul2p(s23, C06));
    ull qp  = fma2(t23, a23, mul2p(t01, a01));
    float qa, qb;
    upk2(qp, qa, qb);
    float q = qa + qb;
    if (H == 8) {
        q += __shfl_xor_sync(0xffffffffu, q, 1);
        q += __shfl_xor_sync(0xffffffffu, q, 2);
    } else {
#pragma unroll
        for (int o = 16; o; o >>= 1) q += __shfl_xor_sync(0xffffffffu, q, o);
    }
    return q;
}

template <int H>
__global__ void __launch_bounds__(256) k_gat_csr(const float* __restrict__ att,
                                                 const float* __restrict__ bias, int slot) {
    int w = (blockIdx.x * blockDim.x + threadIdx.x) >> 5;
    int lane = threadIdx.x & 31;
    float ps = 0.f, ps2 = 0.f;
    if (w < NN) {
        uint2 rraw = *(const uint2*)(g_xrh + (size_t)w * 128 + lane * 4);
        ull r01, r23;
        h4_to_2x2(rraw, r01, r23);
        float4 a4 = ((const float4*)att)[lane];
        ull a01 = pk2(a4.x, a4.y), a23 = pk2(a4.z, a4.w);

        uint2 rawl = *(const uint2*)(g_xlh + (size_t)w * 128 + lane * 4);
        ull l01, l23;
        h4_to_2x2(rawl, l01, l23);
        float m = score2<H>(l01, l23, r01, r23, a01, a23);
        float den = 1.0f;
        ull acc01 = l01, acc23 = l23;

        int b = g_off[w], e = g_off[w + 1];
        int i = b;
        for (; i + 4 <= e; i += 4) {
            int s0 = g_csrc[i], s1 = g_csrc[i + 1], s2 = g_csrc[i + 2], s3 = g_csrc[i + 3];
            uint2 w0r = *(const uint2*)(g_xlh + (size_t)s0 * 128 + lane * 4);
            uint2 w1r = *(const uint2*)(g_xlh + (size_t)s1 * 128 + lane * 4);
            uint2 w2r = *(const uint2*)(g_xlh + (size_t)s2 * 128 + lane * 4);
            uint2 w3r = *(const uint2*)(g_xlh + (size_t)s3 * 128 + lane * 4);
            ull u0a, u0b, u1a, u1b, u2a, u2b, u3a, u3b;
            h4_to_2x2(w0r, u0a, u0b);
            h4_to_2x2(w1r, u1a, u1b);
            h4_to_2x2(w2r, u2a, u2b);
            h4_to_2x2(w3r, u3a, u3b);
            float q0 = score2<H>(u0a, u0b, r01, r23, a01, a23);
            float q1 = score2<H>(u1a, u1b, r01, r23, a01, a23);
            float q2 = score2<H>(u2a, u2b, r01, r23, a01, a23);
            float q3 = score2<H>(u3a, u3b, r01, r23, a01, a23);
            float nm = fmaxf(fmaxf(fmaxf(q0, q1), fmaxf(q2, q3)), m);
            float so = __expf(m - nm);
            float w0 = __expf(q0 - nm), w1 = __expf(q1 - nm);
            float w2 = __expf(q2 - nm), w3 = __expf(q3 - nm);
            den = den * so + w0 + w1 + w2 + w3;
            ull so2 = pk2(so, so);
            ull w0p = pk2(w0, w0), w1p = pk2(w1, w1);
            ull w2p = pk2(w2, w2), w3p = pk2(w3, w3);
            acc01 = mul2p(acc01, so2);
            acc01 = fma2(u0a, w0p, acc01);
            acc01 = fma2(u1a, w1p, acc01);
            acc01 = fma2(u2a, w2p, acc01);
            acc01 = fma2(u3a, w3p, acc01);
            acc23 = mul2p(acc23, so2);
            acc23 = fma2(u0b, w0p, acc23);
            acc23 = fma2(u1b, w1p, acc23);
            acc23 = fma2(u2b, w2p, acc23);
            acc23 = fma2(u3b, w3p, acc23);
            m = nm;
        }
        for (; i < e; i++) {
            uint2 vr = *(const uint2*)(g_xlh + (size_t)g_csrc[i] * 128 + lane * 4);
            ull ua, ub; h4_to_2x2(vr, ua, ub);
            float q = score2<H>(ua, ub, r01, r23, a01, a23);
            float nm = fmaxf(m, q);
            float so = __expf(m - nm), wg = __expf(q - nm);
            den = den * so + wg;
            ull so2 = pk2(so, so), wg2 = pk2(wg, wg);
            acc01 = fma2(ua, wg2, mul2p(acc01, so2));
            acc23 = fma2(ub, wg2, mul2p(acc23, so2));
            m = nm;
        }
        float inv = 1.0f / den;
        float4 b4 = ((const float4*)bias)[lane];
        float ax, ay, az, aw;
        upk2(acc01, ax, ay); upk2(acc23, az, aw);
        ax = ax * inv + b4.x;
        ay = ay * inv + b4.y;
        az = az * inv + b4.z;
        aw = aw * inv + b4.w;
        store_acc_half(w, lane, ax, ay, az, aw);
        ps  = ax + ay + az + aw;
        ps2 = ax * ax + ay * ay + az * az + aw * aw;
    }
    ln_block_reduce(ps, ps2, slot);
}

// ---------------- LayerNorm apply (final layer only; reads half) ----------------
__global__ void k_ln_apply(const float* __restrict__ gm, const float* __restrict__ bt,
                           float* __restrict__ out, int slot) {
    int i = blockIdx.x * blockDim.x + threadIdx.x;   // half2 index
    if (i >= ND / 2) return;
    double mu = g_red[2 * slot] * (1.0 / (double)ND);
    double var = g_red[2 * slot + 1] * (1.0 / (double)ND) - mu * mu;
    float inv = 1.0f / (sqrtf(fmaxf((float)var, 0.0f)) + EPSF);
    float fmu = (float)mu;
    int c = (i * 2) & 127;
    float2 v = __half22float2(((const __half2*)g_acch)[i]);
    out[i * 2 + 0] = (v.x - fmu) * inv * gm[c + 0] + bt[c + 0];
    out[i * 2 + 1] = (v.y - fmu) * inv * gm[c + 1] + bt[c + 1];
}

// ---------------- launch ----------------
static inline int gridFor(long long n, int blk) { return (int)((n + blk - 1) / blk); }

extern "C" void kernel_launch(void* const* d_in, const int* in_sizes, int n_in,
                              void* d_out, int out_size) {
    const float* x   = (const float*)d_in[0];
    const int*   ei  = (const int*)d_in[1];
    const float* W0  = (const float*)d_in[2];
    const float* b0  = (const float*)d_in[3];
    const float* g0  = (const float*)d_in[4];
    const float* be0 = (const float*)d_in[5];
    const float* Wl1 = (const float*)d_in[6];
    const float* bl1 = (const float*)d_in[7];
    const float* Wr1 = (const float*)d_in[8];
    const float* br1 = (const float*)d_in[9];
    const float* att1= (const float*)d_in[10];
    const float* bg1 = (const float*)d_in[11];
    const float* g1  = (const float*)d_in[12];
    const float* be1 = (const float*)d_in[13];
    const float* W2  = (const float*)d_in[14];
    const float* b2  = (const float*)d_in[15];
    const float* g2  = (const float*)d_in[16];
    const float* be2 = (const float*)d_in[17];
    const float* Wl3 = (const float*)d_in[18];
    const float* bl3 = (const float*)d_in[19];
    const float* Wr3 = (const float*)d_in[20];
    const float* br3 = (const float*)d_in[21];
    const float* att3= (const float*)d_in[22];
    const float* bg3 = (const float*)d_in[23];
    const float* g3  = (const float*)d_in[24];
    const float* be3 = (const float*)d_in[25];
    float* out = (float*)d_out;

    const int* src = ei;
    const int* dst = ei + NE;

    const int BLK = 256;
    const int gE   = gridFor(NE, BLK);
    const int gND2 = gridFor(ND / 2, BLK);
    const int gNW  = gridFor((long long)NN * 32, BLK);
    const int nGemmX = gridFor(NN, 128);
    const dim3 gG1(nGemmX, 1), gG2(nGemmX, 2);
    const int nScanBlk = gridFor(NN, 1024);
    const int gInit = gridFor(6 * DD * DD, BLK);
    const int gN256 = gridFor(NN, 256);

    __half* p_xwh; cudaGetSymbolAddress((void**)&p_xwh, g_xwh);
    __half* p_xlh; cudaGetSymbolAddress((void**)&p_xlh, g_xlh);
    __half* p_xrh; cudaGetSymbolAddress((void**)&p_xrh, g_xrh);
    __half* p_acch; cudaGetSymbolAddress((void**)&p_acch, g_acch);
    float* p_dinv; cudaGetSymbolAddress((void**)&p_dinv, g_dinv);
    __half* p_wh; cudaGetSymbolAddress((void**)&p_wh, g_wh);

    const __half* w0h  = p_wh;
    const __half* wl1h = p_wh + 1 * DD * DD;
    const __half* wr1h = p_wh + 2 * DD * DD;
    const __half* w2h  = p_wh + 3 * DD * DD;
    const __half* wl3h = p_wh + 4 * DD * DD;
    const __half* wr3h = p_wh + 5 * DD * DD;

    static bool attr_done = false;
    if (!attr_done) {
        cudaFuncSetAttribute(gemm128t<false, false>,
                             cudaFuncAttributeMaxDynamicSharedMemorySize, GEMM_SMEM);
        cudaFuncSetAttribute(gemm128t<true, false>,
                             cudaFuncAttributeMaxDynamicSharedMemorySize, GEMM_SMEM);
        cudaFuncSetAttribute(gemm128t<true, true>,
                             cudaFuncAttributeMaxDynamicSharedMemorySize, GEMM_SMEM);
        attr_done = true;
    }

    // ---- front: init -> hist -> scan1 -> gemm0 -> scan3 -> scatter
    k_init<<<gInit, BLK>>>(W0, Wl1, Wr1, W2, Wl3, Wr3);
    k_hist<<<gE, BLK>>>(dst);
    k_scan1<<<nScanBlk, 1024>>>();
    gemm128t<false, false><<<gG1, BLK, GEMM_SMEM>>>(x, w0h, nullptr, p_xwh,
                                                    nullptr, nullptr, nullptr, 0,
                                                    nullptr, nullptr, p_dinv);
    k_scan3<<<gN256, 256>>>(nScanBlk);
    k_scatter<<<gE, BLK>>>(src, dst);

    // ---- layer 0: GCN agg ----
    k_gcn_csr<<<gNW, BLK>>>(b0, 0);

    // ---- layer 1: GATv2 (H=8) ----
    gemm128t<true, true><<<gG2, BLK, GEMM_SMEM>>>(p_acch, wl1h, bl1, p_xlh,
                                                  wr1h, br1, p_xrh, 0, g0, be0, nullptr);
    k_gat_csr<8><<<gNW, BLK>>>(att1, bg1, 1);

    // ---- layer 2: GCN ----
    gemm128t<true, false><<<gG1, BLK, GEMM_SMEM>>>(p_acch, w2h, nullptr, p_xwh,
                                                   nullptr, nullptr, nullptr, 1, g1, be1,
                                                   p_dinv);
    k_gcn_csr<<<gNW, BLK>>>(b2, 2);

    // ---- layer 3: GATv2 (H=1) ----
    gemm128t<true, true><<<gG2, BLK, GEMM_SMEM>>>(p_acch, wl3h, bl3, p_xlh,
                                                  wr3h, br3, p_xrh, 2, g2, be2, nullptr);
    k_gat_csr<1><<<gNW, BLK>>>(att3, bg3, 3);

    // ---- final LN -> output ----
    k_ln_apply<<<gND2, BLK>>>(g3, be3, out, 3);
}